// round 13
// baseline (speedup 1.0000x reference)
#include <cuda_runtime.h>
#include <math.h>

// ---------------------------------------------------------------------------
#define BATCH   8
#define CIN     3
#define HH      512
#define WW      512
#define NF      16
#define FEAT    3
#define NUM_IDS 32
#define EPS     1e-5f

#define BUF_ELEMS (8*16*512*512)

__device__ float g_bufA[BUF_ELEMS];
__device__ float g_bufB[BUF_ELEMS];
__device__ float g_mean[8*256];
__device__ float g_istd[8*256];
__device__ float g_ssum[8*256];
__device__ float g_ssq [8*256];
__device__ float g_sums[BATCH*NUM_IDS*FEAT];
__device__ float g_cnt [BATCH*NUM_IDS];

static inline int cdiv(int a, int b) { return (a + b - 1) / b; }
static inline int ilog2(int v) { int r = 0; while ((1 << r) < v) r++; return r; }

#define CO_T 16          // tconv tile
#define CI_CHUNK 16

__device__ __forceinline__ float warp_sum(float v) {
    v += __shfl_down_sync(0xffffffffu, v, 16);
    v += __shfl_down_sync(0xffffffffu, v, 8);
    v += __shfl_down_sync(0xffffffffu, v, 4);
    v += __shfl_down_sync(0xffffffffu, v, 2);
    v += __shfl_down_sync(0xffffffffu, v, 1);
    return v;
}

__device__ __forceinline__ int reflect_idx(int i, int n) {
    return (i < 0) ? -i : ((i >= n) ? 2 * n - 2 - i : i);
}

// ---------------------------------------------------------------------------
// conv 3x3 stride 2 pad 1. COT output channels/thread (templated), 2 same-row
// pixels. ROW-STREAMED input: 3 aligned float2 loads per row, consumed
// immediately. Exact grid; shift/mask; float2 stores; stats fused.
// COT=32 halves total LDG wavefronts vs 16 at ~equal occupancy.
// ---------------------------------------------------------------------------
template<bool NORM, int COT>
__global__ __launch_bounds__(128) void conv3s2_k(
    const float* __restrict__ in, const float* __restrict__ w,
    const float* __restrict__ bias, float* __restrict__ out,
    int Cin, int Cout, int Hin, int Win, int wshift)
{
    const int Hout = Hin >> 1, Wout = Win >> 1;
    const int HWo = Hout * Wout;
    const size_t HWi = (size_t)Hin * Win;
    const int tid = threadIdx.x;
    const int b = blockIdx.z;
    const int co0 = blockIdx.y * COT;
    const int p0 = blockIdx.x * 256 + tid * 2;         // exact grid
    const int oy = p0 >> wshift;
    const int ox = p0 & (Wout - 1);
    const bool py = oy > 0;
    const bool pxl = ox > 0;

    float acc[2][COT];
#pragma unroll
    for (int px = 0; px < 2; px++)
#pragma unroll
        for (int c = 0; c < COT; c++) acc[px][c] = 0.f;

    __shared__ float ws[CI_CHUNK][9][COT];
    __shared__ float sm_m[CI_CHUNK], sm_s[CI_CHUNK];
    __shared__ float red[2 * COT];

    // base: row 2oy-1, col 2ox-2 (8B aligned)
    const float* base0 = in + (size_t)(b * Cin) * HWi +
                         ((size_t)(2 * oy - 1)) * Win + (2 * ox - 2);
    const float2 z2 = make_float2(0.f, 0.f);

    for (int cb = 0; cb < Cin; cb += CI_CHUNK) {
        for (int e = tid; e < CI_CHUNK * 9 * COT; e += 128) {
            int co = e % COT;
            int tap = (e / COT) % 9;
            int ci = e / (COT * 9);
            ws[ci][tap][co] = w[((co0 + co) * Cin + cb + ci) * 9 + tap];
        }
        if (NORM && tid < CI_CHUNK) {
            sm_m[tid] = g_mean[b * Cin + cb + tid];
            sm_s[tid] = g_istd[b * Cin + cb + tid];
        }
        __syncthreads();

        const float* rp = base0 + (size_t)cb * HWi;
        for (int ci = 0; ci < CI_CHUNK; ci++, rp += HWi) {
            float m = 0.f, s = 1.f;
            if (NORM) { m = sm_m[ci]; s = sm_s[ci]; }
#pragma unroll
            for (int r = 0; r < 3; r++) {
                const float2* q = (const float2*)(rp + r * Win);
                bool rowok = (r > 0) || py;
                float2 av = (rowok && pxl) ? __ldg(q)     : z2;
                float2 bv = rowok          ? __ldg(q + 1) : z2;
                float2 cv = rowok          ? __ldg(q + 2) : z2;
                float v[5];
                v[0] = av.y; v[1] = bv.x; v[2] = bv.y; v[3] = cv.x; v[4] = cv.y;
                if (NORM) {
#pragma unroll
                    for (int j = 0; j < 5; j++)
                        v[j] = fmaxf((v[j] - m) * s, 0.f);
                    if (!rowok) { v[0] = v[1] = v[2] = v[3] = v[4] = 0.f; }
                    if (!pxl) v[0] = 0.f;
                }
#pragma unroll
                for (int kx = 0; kx < 3; kx++) {
                    const float t0 = v[kx];
                    const float t1 = v[kx + 2];
#pragma unroll
                    for (int j = 0; j < COT / 4; j++) {
                        const float4 wv = *(const float4*)&ws[ci][r * 3 + kx][4 * j];
                        acc[0][4 * j + 0] += t0 * wv.x;
                        acc[0][4 * j + 1] += t0 * wv.y;
                        acc[0][4 * j + 2] += t0 * wv.z;
                        acc[0][4 * j + 3] += t0 * wv.w;
                        acc[1][4 * j + 0] += t1 * wv.x;
                        acc[1][4 * j + 1] += t1 * wv.y;
                        acc[1][4 * j + 2] += t1 * wv.z;
                        acc[1][4 * j + 3] += t1 * wv.w;
                    }
                }
            }
        }
        __syncthreads();
    }

    if (tid < 2 * COT) red[tid] = 0.f;
    __syncthreads();

    const int lane = tid & 31;
    const size_t obase = ((size_t)(b * Cout + co0)) * HWo;
#pragma unroll
    for (int co = 0; co < COT; co++) {
        float bv = __ldg(bias + co0 + co);
        float v0 = acc[0][co] + bv;
        float v1 = acc[1][co] + bv;
        *(float2*)(out + obase + (size_t)co * HWo + p0) = make_float2(v0, v1);
        float s = warp_sum(v0 + v1);
        float q = warp_sum(v0 * v0 + v1 * v1);
        if (lane == 0) {
            atomicAdd(&red[co], s);
            atomicAdd(&red[COT + co], q);
        }
    }
    __syncthreads();
    for (int c = tid; c < COT; c += 128) {
        atomicAdd(&g_ssum[b * Cout + co0 + c], red[c]);
        atomicAdd(&g_ssq [b * Cout + co0 + c], red[COT + c]);
    }
}

// ---------------------------------------------------------------------------
// ConvTranspose2d k=3 s=2 p=1 op=1, parity-decomposed 2x2 quad per thread.
// Output stored as 2 aligned float2 per channel. CI_CHUNK=16, CO_T=16.
// ---------------------------------------------------------------------------
template<bool NORM>
__global__ __launch_bounds__(128) void tconv3s2_k(
    const float* __restrict__ in, const float* __restrict__ w,
    const float* __restrict__ bias, float* __restrict__ out,
    int Cin, int Cout, int Hin, int Win, int wshift)
{
    const size_t HWi = (size_t)Hin * Win;
    const int q = blockIdx.x * blockDim.x + threadIdx.x;
    const int b = blockIdx.z;
    const int co0 = blockIdx.y * CO_T;
    const int m = q >> wshift;
    const int n = q & (Win - 1);
    const bool hx = (n + 1) < Win;
    const bool hy = (m + 1) < Hin;

    float acc[4][CO_T];
#pragma unroll
    for (int p = 0; p < 4; p++)
#pragma unroll
        for (int c = 0; c < CO_T; c++) acc[p][c] = 0.f;

    __shared__ float ws[CI_CHUNK][9][CO_T];
    __shared__ float sm_m[CI_CHUNK], sm_s[CI_CHUNK];
    __shared__ float red[2 * CO_T];

    const float* base0 = in + (size_t)(b * Cin) * HWi + (size_t)m * Win + n;

    for (int cb = 0; cb < Cin; cb += CI_CHUNK) {
        for (int e = threadIdx.x; e < CI_CHUNK * 9 * CO_T; e += 128) {
            int co = e % CO_T;
            int tap = (e / CO_T) % 9;
            int ci = e / (CO_T * 9);
            ws[ci][tap][co] = w[((size_t)(cb + ci) * Cout + co0 + co) * 9 + tap];
        }
        if (NORM && threadIdx.x < CI_CHUNK) {
            sm_m[threadIdx.x] = g_mean[b * Cin + cb + threadIdx.x];
            sm_s[threadIdx.x] = g_istd[b * Cin + cb + threadIdx.x];
        }
        __syncthreads();

        const float* r0 = base0 + (size_t)cb * HWi;
        for (int ci = 0; ci < CI_CHUNK; ci++, r0 += HWi) {
            float mm = 0.f, sc = 1.f;
            if (NORM) { mm = sm_m[ci]; sc = sm_s[ci]; }
            float v00 = __ldg(r0);
            float v01 = hx ? __ldg(r0 + 1) : 0.f;
            float v10 = hy ? __ldg(r0 + Win) : 0.f;
            float v11 = (hx && hy) ? __ldg(r0 + Win + 1) : 0.f;
            if (NORM) {
                v00 = fmaxf((v00 - mm) * sc, 0.f);
                v01 = fmaxf((v01 - mm) * sc, 0.f);
                v10 = fmaxf((v10 - mm) * sc, 0.f);
                v11 = fmaxf((v11 - mm) * sc, 0.f);
                if (!hx) { v01 = 0.f; v11 = 0.f; }
                if (!hy) { v10 = 0.f; v11 = 0.f; }
            }
            const float vals[9] = {v00, v01, v00, v10, v00, v11, v10, v01, v00};
            const int taps[9]  = {4, 3, 5, 1, 7, 0, 2, 6, 8};
            const int quads[9] = {0, 1, 1, 2, 2, 3, 3, 3, 3};
#pragma unroll
            for (int k = 0; k < 9; k++) {
                const float4 w0 = *(const float4*)&ws[ci][taps[k]][0];
                const float4 w1 = *(const float4*)&ws[ci][taps[k]][4];
                const float4 w2 = *(const float4*)&ws[ci][taps[k]][8];
                const float4 w3 = *(const float4*)&ws[ci][taps[k]][12];
                const float t = vals[k];
                float* a = acc[quads[k]];
                a[0]  += t * w0.x; a[1]  += t * w0.y; a[2]  += t * w0.z; a[3]  += t * w0.w;
                a[4]  += t * w1.x; a[5]  += t * w1.y; a[6]  += t * w1.z; a[7]  += t * w1.w;
                a[8]  += t * w2.x; a[9]  += t * w2.y; a[10] += t * w2.z; a[11] += t * w2.w;
                a[12] += t * w3.x; a[13] += t * w3.y; a[14] += t * w3.z; a[15] += t * w3.w;
            }
        }
        __syncthreads();
    }

    if (threadIdx.x < 2 * CO_T) red[threadIdx.x] = 0.f;
    __syncthreads();

    const int Hout = 2 * Hin, Wout = 2 * Win;
    const int lane = threadIdx.x & 31;
#pragma unroll
    for (int co = 0; co < CO_T; co++) {
        float bv = __ldg(bias + co0 + co);
        float o0 = acc[0][co] + bv, o1 = acc[1][co] + bv;
        float o2 = acc[2][co] + bv, o3 = acc[3][co] + bv;
        size_t base = ((size_t)(b * Cout + co0 + co)) * Hout * Wout;
        size_t p00 = base + (size_t)(2 * m) * Wout + 2 * n;   // even -> aligned
        *(float2*)(out + p00)        = make_float2(o0, o1);
        *(float2*)(out + p00 + Wout) = make_float2(o2, o3);
        float s = warp_sum(o0 + o1 + o2 + o3);
        float qq = warp_sum(o0 * o0 + o1 * o1 + o2 * o2 + o3 * o3);
        if (lane == 0) {
            atomicAdd(&red[co], s);
            atomicAdd(&red[CO_T + co], qq);
        }
    }
    __syncthreads();
    if (threadIdx.x < CO_T) {
        atomicAdd(&g_ssum[b * Cout + co0 + threadIdx.x], red[threadIdx.x]);
        atomicAdd(&g_ssq [b * Cout + co0 + threadIdx.x], red[CO_T + threadIdx.x]);
    }
}

// ---------------------------------------------------------------------------
// 7x7 reflect conv, first layer (3 -> 16), raw input. One row per block,
// 4 px/thread, all 16 channels. Stats fused.
// ---------------------------------------------------------------------------
__global__ __launch_bounds__(128) void conv7_in_k(
    const float* __restrict__ in, const float* __restrict__ w,
    const float* __restrict__ bias, float* __restrict__ out)
{
    const int W = WW, H = HH;
    const int tid = threadIdx.x;
    const int b = blockIdx.y;
    const int oy = blockIdx.x;
    const int ox0 = tid * 4;

    __shared__ float ws[CIN][49][16];
    __shared__ float red[32];
    for (int e = tid; e < CIN * 49 * 16; e += 128) {
        int co = e % 16;
        int tap = (e / 16) % 49;
        int ci = e / (16 * 49);
        ws[ci][tap][co] = w[(co * CIN + ci) * 49 + tap];
    }
    __syncthreads();

    float acc[4][16];
#pragma unroll
    for (int px = 0; px < 4; px++)
#pragma unroll
        for (int c = 0; c < 16; c++) acc[px][c] = 0.f;

    for (int ci = 0; ci < CIN; ci++) {
        const float* ip = in + ((size_t)(b * CIN + ci)) * H * W;
#pragma unroll
        for (int ky = 0; ky < 7; ky++) {
            int iy = reflect_idx(oy - 3 + ky, H);
            const float* row = ip + (size_t)iy * W;
            float vv[10];
#pragma unroll
            for (int k = 0; k < 10; k++) {
                int ix = reflect_idx(ox0 - 3 + k, W);
                vv[k] = __ldg(row + ix);
            }
#pragma unroll
            for (int kx = 0; kx < 7; kx++) {
                const float4 w0 = *(const float4*)&ws[ci][ky * 7 + kx][0];
                const float4 w1 = *(const float4*)&ws[ci][ky * 7 + kx][4];
                const float4 w2 = *(const float4*)&ws[ci][ky * 7 + kx][8];
                const float4 w3 = *(const float4*)&ws[ci][ky * 7 + kx][12];
#pragma unroll
                for (int px = 0; px < 4; px++) {
                    const float t = vv[kx + px];
                    acc[px][0]  += t * w0.x; acc[px][1]  += t * w0.y;
                    acc[px][2]  += t * w0.z; acc[px][3]  += t * w0.w;
                    acc[px][4]  += t * w1.x; acc[px][5]  += t * w1.y;
                    acc[px][6]  += t * w1.z; acc[px][7]  += t * w1.w;
                    acc[px][8]  += t * w2.x; acc[px][9]  += t * w2.y;
                    acc[px][10] += t * w2.z; acc[px][11] += t * w2.w;
                    acc[px][12] += t * w3.x; acc[px][13] += t * w3.y;
                    acc[px][14] += t * w3.z; acc[px][15] += t * w3.w;
                }
            }
        }
    }

    if (tid < 32) red[tid] = 0.f;
    __syncthreads();

    const int lane = tid & 31;
#pragma unroll
    for (int co = 0; co < 16; co++) {
        float bv = __ldg(bias + co);
        float v0 = acc[0][co] + bv, v1 = acc[1][co] + bv;
        float v2 = acc[2][co] + bv, v3 = acc[3][co] + bv;
        size_t base = ((size_t)(b * NF + co)) * H * W + (size_t)oy * W + ox0;
        *(float4*)(out + base) = make_float4(v0, v1, v2, v3);
        float s = warp_sum(v0 + v1 + v2 + v3);
        float q = warp_sum(v0 * v0 + v1 * v1 + v2 * v2 + v3 * v3);
        if (lane == 0) {
            atomicAdd(&red[co], s);
            atomicAdd(&red[16 + co], q);
        }
    }
    __syncthreads();
    if (tid < 16) {
        atomicAdd(&g_ssum[b * NF + tid], red[tid]);
        atomicAdd(&g_ssq [b * NF + tid], red[16 + tid]);
    }
}

// ---------------------------------------------------------------------------
// 7x7 reflect conv, last layer (16 -> 3) + tanh + FUSED instance pooling.
// ---------------------------------------------------------------------------
__global__ __launch_bounds__(128) void conv7_out_k(
    const float* __restrict__ in, const int* __restrict__ ids,
    const float* __restrict__ w, const float* __restrict__ bias)
{
    const int W = WW, H = HH;
    const int tid = threadIdx.x;
    const int b = blockIdx.y;
    const int oy = blockIdx.x;
    const int ox0 = tid * 4;

    __shared__ float ws[NF][49][4];
    __shared__ float p_sum[NUM_IDS * FEAT];
    __shared__ float p_cnt[NUM_IDS];
    for (int e = tid; e < NF * 49 * 4; e += 128) {
        int co = e % 4;
        int tap = (e / 4) % 49;
        int ci = e / (4 * 49);
        ws[ci][tap][co] = (co < FEAT) ? w[(co * NF + ci) * 49 + tap] : 0.f;
    }
    if (tid < NUM_IDS * FEAT) p_sum[tid] = 0.f;
    if (tid < NUM_IDS) p_cnt[tid] = 0.f;
    __syncthreads();

    float acc[4][3];
#pragma unroll
    for (int px = 0; px < 4; px++)
#pragma unroll
        for (int c = 0; c < 3; c++) acc[px][c] = 0.f;

    for (int ci = 0; ci < NF; ci++) {
        const float m = g_mean[b * NF + ci];
        const float s = g_istd[b * NF + ci];
        const float* ip = in + ((size_t)(b * NF + ci)) * H * W;
#pragma unroll
        for (int ky = 0; ky < 7; ky++) {
            int iy = reflect_idx(oy - 3 + ky, H);
            const float* row = ip + (size_t)iy * W;
            float vv[10];
#pragma unroll
            for (int k = 0; k < 10; k++) {
                int ix = reflect_idx(ox0 - 3 + k, W);
                vv[k] = fmaxf((__ldg(row + ix) - m) * s, 0.f);
            }
#pragma unroll
            for (int kx = 0; kx < 7; kx++) {
                const float4 wv = *(const float4*)&ws[ci][ky * 7 + kx][0];
#pragma unroll
                for (int px = 0; px < 4; px++) {
                    const float t = vv[kx + px];
                    acc[px][0] += t * wv.x;
                    acc[px][1] += t * wv.y;
                    acc[px][2] += t * wv.z;
                }
            }
        }
    }

    const int* idrow = ids + (size_t)b * H * W + (size_t)oy * W + ox0;
#pragma unroll
    for (int px = 0; px < 4; px++) {
        int id = idrow[px];
        atomicAdd(&p_cnt[id], 1.f);
#pragma unroll
        for (int c = 0; c < 3; c++) {
            float v = tanhf(acc[px][c] + __ldg(bias + c));
            atomicAdd(&p_sum[id * FEAT + c], v);
        }
    }
    __syncthreads();
    if (tid < NUM_IDS * FEAT) atomicAdd(&g_sums[b * NUM_IDS * FEAT + tid], p_sum[tid]);
    if (tid < NUM_IDS) atomicAdd(&g_cnt[b * NUM_IDS + tid], p_cnt[tid]);
}

// ---------------------------------------------------------------------------
__global__ void prenorm_k(float* __restrict__ x, int HW4, int total4)
{
    int i = blockIdx.x * blockDim.x + threadIdx.x;
    if (i >= total4) return;
    int bc = i / HW4;
    float m = g_mean[bc], s = g_istd[bc];
    float4 v = ((float4*)x)[i];
    v.x = fmaxf((v.x - m) * s, 0.f);
    v.y = fmaxf((v.y - m) * s, 0.f);
    v.z = fmaxf((v.z - m) * s, 0.f);
    v.w = fmaxf((v.w - m) * s, 0.f);
    ((float4*)x)[i] = v;
}

__global__ void stats_final(int n, int HW)
{
    int i = blockIdx.x * blockDim.x + threadIdx.x;
    if (i >= n) return;
    float m = g_ssum[i] / (float)HW;
    float var = g_ssq[i] / (float)HW - m * m;
    g_mean[i] = m;
    g_istd[i] = rsqrtf(var + EPS);
    g_ssum[i] = 0.f;
    g_ssq[i] = 0.f;
}

__global__ void pool_zero()
{
    int i = blockIdx.x * blockDim.x + threadIdx.x;
    if (i < BATCH * NUM_IDS * FEAT) g_sums[i] = 0.f;
    if (i < BATCH * NUM_IDS) g_cnt[i] = 0.f;
}

__global__ void pool_finalize()
{
    int i = blockIdx.x * blockDim.x + threadIdx.x;
    if (i >= BATCH * NUM_IDS) return;
    float c = g_cnt[i];
    float inv = 1.f / fmaxf(c, 1.f);
#pragma unroll
    for (int k = 0; k < FEAT; k++) g_sums[i * FEAT + k] *= inv;
}

__global__ void pool_scatter(const int* __restrict__ ids,
                             float* __restrict__ out, int HW)
{
    int idx = blockIdx.x * blockDim.x + threadIdx.x;
    int total4 = BATCH * HW / 4;
    if (idx >= total4) return;
    int hw4 = HW / 4;
    int bb = idx / hw4;
    int p4 = (idx % hw4) * 4;
    int4 id4 = ((const int4*)(ids + (size_t)bb * HW))[idx % hw4];
    const float* sb = g_sums + bb * NUM_IDS * FEAT;
#pragma unroll
    for (int c = 0; c < FEAT; c++) {
        float4 v;
        v.x = sb[id4.x * FEAT + c];
        v.y = sb[id4.y * FEAT + c];
        v.z = sb[id4.z * FEAT + c];
        v.w = sb[id4.w * FEAT + c];
        *(float4*)(out + ((size_t)bb * FEAT + c) * HW + p4) = v;
    }
}

// ---------------------------------------------------------------------------
extern "C" void kernel_launch(void* const* d_in, const int* in_sizes, int n_in,
                              void* d_out, int out_size)
{
    const float* x     = (const float*)d_in[0];
    const int*   imap  = (const int*)  d_in[1];
    const float* w_in  = (const float*)d_in[2];
    const float* b_in  = (const float*)d_in[3];
    const float* w_d[4], *b_d[4], *w_u[4], *b_u[4];
    for (int i = 0; i < 4; i++) {
        w_d[i] = (const float*)d_in[4 + 2 * i];
        b_d[i] = (const float*)d_in[5 + 2 * i];
        w_u[i] = (const float*)d_in[12 + 2 * i];
        b_u[i] = (const float*)d_in[13 + 2 * i];
    }
    const float* w_out = (const float*)d_in[20];
    const float* b_out = (const float*)d_in[21];
    float* out = (float*)d_out;

    float* A; float* B;
    cudaGetSymbolAddress((void**)&A, g_bufA);
    cudaGetSymbolAddress((void**)&B, g_bufB);

    pool_zero<<<cdiv(BATCH * NUM_IDS * FEAT, 256), 256>>>();

    // 1) in conv
    {
        dim3 grid(HH, BATCH);
        conv7_in_k<<<grid, 128>>>(x, w_in, b_in, A);
        stats_final<<<1, 128>>>(BATCH * NF, HH * WW);
    }

    // 2) down path; i>=2 prenorm. CO tile 32 everywhere (Cout >= 32).
    float* src = A; float* dst = B;
    int C = NF, H = HH, W = WW;
    for (int i = 0; i < 4; i++) {
        int Cout = 2 * C, Ho = H / 2, Wo = W / 2;
        dim3 grid((Ho * Wo) / 256, Cout / 32, BATCH);
        int wsh = ilog2(Wo);
        if (i >= 2) {
            int total4 = BATCH * C * H * W / 4;
            prenorm_k<<<cdiv(total4, 256), 256>>>(src, H * W / 4, total4);
            conv3s2_k<false, 32><<<grid, 128>>>(src, w_d[i], b_d[i], dst, C, Cout, H, W, wsh);
        } else {
            conv3s2_k<true, 32><<<grid, 128>>>(src, w_d[i], b_d[i], dst, C, Cout, H, W, wsh);
        }
        stats_final<<<cdiv(BATCH * Cout, 128), 128>>>(BATCH * Cout, Ho * Wo);
        float* t = src; src = dst; dst = t;
        C = Cout; H = Ho; W = Wo;
    }

    // 3) up path; i<=1 prenorm
    for (int i = 0; i < 4; i++) {
        int Cout = C / 2, Ho = 2 * H, Wo = 2 * W;
        dim3 grid((H * W) / 128, Cout / CO_T, BATCH);
        int wsh = ilog2(W);
        if (i <= 1) {
            int total4 = BATCH * C * H * W / 4;
            prenorm_k<<<cdiv(total4, 256), 256>>>(src, H * W / 4, total4);
            tconv3s2_k<false><<<grid, 128>>>(src, w_u[i], b_u[i], dst, C, Cout, H, W, wsh);
        } else {
            tconv3s2_k<true><<<grid, 128>>>(src, w_u[i], b_u[i], dst, C, Cout, H, W, wsh);
        }
        stats_final<<<cdiv(BATCH * Cout, 128), 128>>>(BATCH * Cout, Ho * Wo);
        float* t = src; src = dst; dst = t;
        C = Cout; H = Ho; W = Wo;
    }

    // 4) out conv + tanh + fused pooling
    {
        dim3 grid(HH, BATCH);
        conv7_out_k<<<grid, 128>>>(src, imap, w_out, b_out);
    }

    // 5) finalize + scatter
    pool_finalize<<<1, 256>>>();
    pool_scatter<<<cdiv(BATCH * HH * WW / 4, 256), 256>>>(imap, out, HH * WW);
}

// round 14
// speedup vs baseline: 1.0286x; 1.0286x over previous
#include <cuda_runtime.h>
#include <math.h>

// ---------------------------------------------------------------------------
#define BATCH   8
#define CIN     3
#define HH      512
#define WW      512
#define NF      16
#define FEAT    3
#define NUM_IDS 32
#define EPS     1e-5f

#define BUF_ELEMS (8*16*512*512)

__device__ float g_bufA[BUF_ELEMS];
__device__ float g_bufB[BUF_ELEMS];
__device__ float g_mean[8*256];
__device__ float g_istd[8*256];
__device__ float g_ssum[8*256];
__device__ float g_ssq [8*256];
__device__ float g_sums[BATCH*NUM_IDS*FEAT];
__device__ float g_cnt [BATCH*NUM_IDS];

static inline int cdiv(int a, int b) { return (a + b - 1) / b; }
static inline int ilog2(int v) { int r = 0; while ((1 << r) < v) r++; return r; }

#define CO_T 16
#define CI_CHUNK 16

__device__ __forceinline__ float warp_sum(float v) {
    v += __shfl_down_sync(0xffffffffu, v, 16);
    v += __shfl_down_sync(0xffffffffu, v, 8);
    v += __shfl_down_sync(0xffffffffu, v, 4);
    v += __shfl_down_sync(0xffffffffu, v, 2);
    v += __shfl_down_sync(0xffffffffu, v, 1);
    return v;
}

__device__ __forceinline__ int reflect_idx(int i, int n) {
    return (i < 0) ? -i : ((i >= n) ? 2 * n - 2 - i : i);
}

// ---------------------------------------------------------------------------
// conv 3x3 stride 2 pad 1. 16 output channels/thread, 2 same-row pixels.
// ROW-STREAMED input: 3 aligned float2 loads per row, consumed immediately.
// Exact grid; shift/mask; float2 stores; stats fused.  (R11/R12 best config)
// ---------------------------------------------------------------------------
template<bool NORM>
__global__ __launch_bounds__(128) void conv3s2_k(
    const float* __restrict__ in, const float* __restrict__ w,
    const float* __restrict__ bias, float* __restrict__ out,
    int Cin, int Cout, int Hin, int Win, int wshift)
{
    const int Hout = Hin >> 1, Wout = Win >> 1;
    const int HWo = Hout * Wout;
    const size_t HWi = (size_t)Hin * Win;
    const int tid = threadIdx.x;
    const int b = blockIdx.z;
    const int co0 = blockIdx.y * CO_T;
    const int p0 = blockIdx.x * 256 + tid * 2;         // exact grid
    const int oy = p0 >> wshift;
    const int ox = p0 & (Wout - 1);
    const bool py = oy > 0;
    const bool pxl = ox > 0;

    float acc[2][CO_T];
#pragma unroll
    for (int px = 0; px < 2; px++)
#pragma unroll
        for (int c = 0; c < CO_T; c++) acc[px][c] = 0.f;

    __shared__ float ws[CI_CHUNK][9][CO_T];
    __shared__ float sm_m[CI_CHUNK], sm_s[CI_CHUNK];
    __shared__ float red[2 * CO_T];

    // base: row 2oy-1, col 2ox-2 (8B aligned)
    const float* base0 = in + (size_t)(b * Cin) * HWi +
                         ((size_t)(2 * oy - 1)) * Win + (2 * ox - 2);
    const float2 z2 = make_float2(0.f, 0.f);

    for (int cb = 0; cb < Cin; cb += CI_CHUNK) {
        for (int e = tid; e < CI_CHUNK * 9 * CO_T; e += 128) {
            int co = e % CO_T;
            int tap = (e / CO_T) % 9;
            int ci = e / (CO_T * 9);
            ws[ci][tap][co] = w[((co0 + co) * Cin + cb + ci) * 9 + tap];
        }
        if (NORM && tid < CI_CHUNK) {
            sm_m[tid] = g_mean[b * Cin + cb + tid];
            sm_s[tid] = g_istd[b * Cin + cb + tid];
        }
        __syncthreads();

        const float* rp = base0 + (size_t)cb * HWi;
        for (int ci = 0; ci < CI_CHUNK; ci++, rp += HWi) {
            float m = 0.f, s = 1.f;
            if (NORM) { m = sm_m[ci]; s = sm_s[ci]; }
#pragma unroll
            for (int r = 0; r < 3; r++) {
                const float2* q = (const float2*)(rp + r * Win);
                bool rowok = (r > 0) || py;
                float2 av = (rowok && pxl) ? __ldg(q)     : z2;
                float2 bv = rowok          ? __ldg(q + 1) : z2;
                float2 cv = rowok          ? __ldg(q + 2) : z2;
                float v[5];
                v[0] = av.y; v[1] = bv.x; v[2] = bv.y; v[3] = cv.x; v[4] = cv.y;
                if (NORM) {
#pragma unroll
                    for (int j = 0; j < 5; j++)
                        v[j] = fmaxf((v[j] - m) * s, 0.f);
                    if (!rowok) { v[0] = v[1] = v[2] = v[3] = v[4] = 0.f; }
                    if (!pxl) v[0] = 0.f;
                }
#pragma unroll
                for (int kx = 0; kx < 3; kx++) {
                    const float4 w0 = *(const float4*)&ws[ci][r * 3 + kx][0];
                    const float4 w1 = *(const float4*)&ws[ci][r * 3 + kx][4];
                    const float4 w2 = *(const float4*)&ws[ci][r * 3 + kx][8];
                    const float4 w3 = *(const float4*)&ws[ci][r * 3 + kx][12];
                    const float t0 = v[kx];
                    const float t1 = v[kx + 2];
                    acc[0][0]  += t0 * w0.x; acc[0][1]  += t0 * w0.y;
                    acc[0][2]  += t0 * w0.z; acc[0][3]  += t0 * w0.w;
                    acc[0][4]  += t0 * w1.x; acc[0][5]  += t0 * w1.y;
                    acc[0][6]  += t0 * w1.z; acc[0][7]  += t0 * w1.w;
                    acc[0][8]  += t0 * w2.x; acc[0][9]  += t0 * w2.y;
                    acc[0][10] += t0 * w2.z; acc[0][11] += t0 * w2.w;
                    acc[0][12] += t0 * w3.x; acc[0][13] += t0 * w3.y;
                    acc[0][14] += t0 * w3.z; acc[0][15] += t0 * w3.w;
                    acc[1][0]  += t1 * w0.x; acc[1][1]  += t1 * w0.y;
                    acc[1][2]  += t1 * w0.z; acc[1][3]  += t1 * w0.w;
                    acc[1][4]  += t1 * w1.x; acc[1][5]  += t1 * w1.y;
                    acc[1][6]  += t1 * w1.z; acc[1][7]  += t1 * w1.w;
                    acc[1][8]  += t1 * w2.x; acc[1][9]  += t1 * w2.y;
                    acc[1][10] += t1 * w2.z; acc[1][11] += t1 * w2.w;
                    acc[1][12] += t1 * w3.x; acc[1][13] += t1 * w3.y;
                    acc[1][14] += t1 * w3.z; acc[1][15] += t1 * w3.w;
                }
            }
        }
        __syncthreads();
    }

    if (tid < 2 * CO_T) red[tid] = 0.f;
    __syncthreads();

    const int lane = tid & 31;
    const size_t obase = ((size_t)(b * Cout + co0)) * HWo;
#pragma unroll
    for (int co = 0; co < CO_T; co++) {
        float bv = __ldg(bias + co0 + co);
        float v0 = acc[0][co] + bv;
        float v1 = acc[1][co] + bv;
        *(float2*)(out + obase + (size_t)co * HWo + p0) = make_float2(v0, v1);
        float s = warp_sum(v0 + v1);
        float q = warp_sum(v0 * v0 + v1 * v1);
        if (lane == 0) {
            atomicAdd(&red[co], s);
            atomicAdd(&red[CO_T + co], q);
        }
    }
    __syncthreads();
    if (tid < CO_T) {
        atomicAdd(&g_ssum[b * Cout + co0 + tid], red[tid]);
        atomicAdd(&g_ssq [b * Cout + co0 + tid], red[CO_T + tid]);
    }
}

// ---------------------------------------------------------------------------
// ConvTranspose2d k=3 s=2 p=1 op=1, parity-decomposed 2x2 quad per thread.
// Output stored as 2 aligned float2 per channel. CI_CHUNK=16, CO_T=16.
// ---------------------------------------------------------------------------
template<bool NORM>
__global__ __launch_bounds__(128) void tconv3s2_k(
    const float* __restrict__ in, const float* __restrict__ w,
    const float* __restrict__ bias, float* __restrict__ out,
    int Cin, int Cout, int Hin, int Win, int wshift)
{
    const size_t HWi = (size_t)Hin * Win;
    const int q = blockIdx.x * blockDim.x + threadIdx.x;
    const int b = blockIdx.z;
    const int co0 = blockIdx.y * CO_T;
    const int m = q >> wshift;
    const int n = q & (Win - 1);
    const bool hx = (n + 1) < Win;
    const bool hy = (m + 1) < Hin;

    float acc[4][CO_T];
#pragma unroll
    for (int p = 0; p < 4; p++)
#pragma unroll
        for (int c = 0; c < CO_T; c++) acc[p][c] = 0.f;

    __shared__ float ws[CI_CHUNK][9][CO_T];
    __shared__ float sm_m[CI_CHUNK], sm_s[CI_CHUNK];
    __shared__ float red[2 * CO_T];

    const float* base0 = in + (size_t)(b * Cin) * HWi + (size_t)m * Win + n;

    for (int cb = 0; cb < Cin; cb += CI_CHUNK) {
        for (int e = threadIdx.x; e < CI_CHUNK * 9 * CO_T; e += 128) {
            int co = e % CO_T;
            int tap = (e / CO_T) % 9;
            int ci = e / (CO_T * 9);
            ws[ci][tap][co] = w[((size_t)(cb + ci) * Cout + co0 + co) * 9 + tap];
        }
        if (NORM && threadIdx.x < CI_CHUNK) {
            sm_m[threadIdx.x] = g_mean[b * Cin + cb + threadIdx.x];
            sm_s[threadIdx.x] = g_istd[b * Cin + cb + threadIdx.x];
        }
        __syncthreads();

        const float* r0 = base0 + (size_t)cb * HWi;
        for (int ci = 0; ci < CI_CHUNK; ci++, r0 += HWi) {
            float mm = 0.f, sc = 1.f;
            if (NORM) { mm = sm_m[ci]; sc = sm_s[ci]; }
            float v00 = __ldg(r0);
            float v01 = hx ? __ldg(r0 + 1) : 0.f;
            float v10 = hy ? __ldg(r0 + Win) : 0.f;
            float v11 = (hx && hy) ? __ldg(r0 + Win + 1) : 0.f;
            if (NORM) {
                v00 = fmaxf((v00 - mm) * sc, 0.f);
                v01 = fmaxf((v01 - mm) * sc, 0.f);
                v10 = fmaxf((v10 - mm) * sc, 0.f);
                v11 = fmaxf((v11 - mm) * sc, 0.f);
                if (!hx) { v01 = 0.f; v11 = 0.f; }
                if (!hy) { v10 = 0.f; v11 = 0.f; }
            }
            const float vals[9] = {v00, v01, v00, v10, v00, v11, v10, v01, v00};
            const int taps[9]  = {4, 3, 5, 1, 7, 0, 2, 6, 8};
            const int quads[9] = {0, 1, 1, 2, 2, 3, 3, 3, 3};
#pragma unroll
            for (int k = 0; k < 9; k++) {
                const float4 w0 = *(const float4*)&ws[ci][taps[k]][0];
                const float4 w1 = *(const float4*)&ws[ci][taps[k]][4];
                const float4 w2 = *(const float4*)&ws[ci][taps[k]][8];
                const float4 w3 = *(const float4*)&ws[ci][taps[k]][12];
                const float t = vals[k];
                float* a = acc[quads[k]];
                a[0]  += t * w0.x; a[1]  += t * w0.y; a[2]  += t * w0.z; a[3]  += t * w0.w;
                a[4]  += t * w1.x; a[5]  += t * w1.y; a[6]  += t * w1.z; a[7]  += t * w1.w;
                a[8]  += t * w2.x; a[9]  += t * w2.y; a[10] += t * w2.z; a[11] += t * w2.w;
                a[12] += t * w3.x; a[13] += t * w3.y; a[14] += t * w3.z; a[15] += t * w3.w;
            }
        }
        __syncthreads();
    }

    if (threadIdx.x < 2 * CO_T) red[threadIdx.x] = 0.f;
    __syncthreads();

    const int Hout = 2 * Hin, Wout = 2 * Win;
    const int lane = threadIdx.x & 31;
#pragma unroll
    for (int co = 0; co < CO_T; co++) {
        float bv = __ldg(bias + co0 + co);
        float o0 = acc[0][co] + bv, o1 = acc[1][co] + bv;
        float o2 = acc[2][co] + bv, o3 = acc[3][co] + bv;
        size_t base = ((size_t)(b * Cout + co0 + co)) * Hout * Wout;
        size_t p00 = base + (size_t)(2 * m) * Wout + 2 * n;   // even -> aligned
        *(float2*)(out + p00)        = make_float2(o0, o1);
        *(float2*)(out + p00 + Wout) = make_float2(o2, o3);
        float s = warp_sum(o0 + o1 + o2 + o3);
        float qq = warp_sum(o0 * o0 + o1 * o1 + o2 * o2 + o3 * o3);
        if (lane == 0) {
            atomicAdd(&red[co], s);
            atomicAdd(&red[CO_T + co], qq);
        }
    }
    __syncthreads();
    if (threadIdx.x < CO_T) {
        atomicAdd(&g_ssum[b * Cout + co0 + threadIdx.x], red[threadIdx.x]);
        atomicAdd(&g_ssq [b * Cout + co0 + threadIdx.x], red[CO_T + threadIdx.x]);
    }
}

// ---------------------------------------------------------------------------
// 7x7 reflect conv, first layer (3 -> 16), raw input. One row per block,
// 4 px/thread, all 16 channels. Stats fused.
// ---------------------------------------------------------------------------
__global__ __launch_bounds__(128) void conv7_in_k(
    const float* __restrict__ in, const float* __restrict__ w,
    const float* __restrict__ bias, float* __restrict__ out)
{
    const int W = WW, H = HH;
    const int tid = threadIdx.x;
    const int b = blockIdx.y;
    const int oy = blockIdx.x;
    const int ox0 = tid * 4;

    __shared__ float ws[CIN][49][16];
    __shared__ float red[32];
    for (int e = tid; e < CIN * 49 * 16; e += 128) {
        int co = e % 16;
        int tap = (e / 16) % 49;
        int ci = e / (16 * 49);
        ws[ci][tap][co] = w[(co * CIN + ci) * 49 + tap];
    }
    __syncthreads();

    float acc[4][16];
#pragma unroll
    for (int px = 0; px < 4; px++)
#pragma unroll
        for (int c = 0; c < 16; c++) acc[px][c] = 0.f;

    for (int ci = 0; ci < CIN; ci++) {
        const float* ip = in + ((size_t)(b * CIN + ci)) * H * W;
#pragma unroll
        for (int ky = 0; ky < 7; ky++) {
            int iy = reflect_idx(oy - 3 + ky, H);
            const float* row = ip + (size_t)iy * W;
            float vv[10];
#pragma unroll
            for (int k = 0; k < 10; k++) {
                int ix = reflect_idx(ox0 - 3 + k, W);
                vv[k] = __ldg(row + ix);
            }
#pragma unroll
            for (int kx = 0; kx < 7; kx++) {
                const float4 w0 = *(const float4*)&ws[ci][ky * 7 + kx][0];
                const float4 w1 = *(const float4*)&ws[ci][ky * 7 + kx][4];
                const float4 w2 = *(const float4*)&ws[ci][ky * 7 + kx][8];
                const float4 w3 = *(const float4*)&ws[ci][ky * 7 + kx][12];
#pragma unroll
                for (int px = 0; px < 4; px++) {
                    const float t = vv[kx + px];
                    acc[px][0]  += t * w0.x; acc[px][1]  += t * w0.y;
                    acc[px][2]  += t * w0.z; acc[px][3]  += t * w0.w;
                    acc[px][4]  += t * w1.x; acc[px][5]  += t * w1.y;
                    acc[px][6]  += t * w1.z; acc[px][7]  += t * w1.w;
                    acc[px][8]  += t * w2.x; acc[px][9]  += t * w2.y;
                    acc[px][10] += t * w2.z; acc[px][11] += t * w2.w;
                    acc[px][12] += t * w3.x; acc[px][13] += t * w3.y;
                    acc[px][14] += t * w3.z; acc[px][15] += t * w3.w;
                }
            }
        }
    }

    if (tid < 32) red[tid] = 0.f;
    __syncthreads();

    const int lane = tid & 31;
#pragma unroll
    for (int co = 0; co < 16; co++) {
        float bv = __ldg(bias + co);
        float v0 = acc[0][co] + bv, v1 = acc[1][co] + bv;
        float v2 = acc[2][co] + bv, v3 = acc[3][co] + bv;
        size_t base = ((size_t)(b * NF + co)) * H * W + (size_t)oy * W + ox0;
        *(float4*)(out + base) = make_float4(v0, v1, v2, v3);
        float s = warp_sum(v0 + v1 + v2 + v3);
        float q = warp_sum(v0 * v0 + v1 * v1 + v2 * v2 + v3 * v3);
        if (lane == 0) {
            atomicAdd(&red[co], s);
            atomicAdd(&red[16 + co], q);
        }
    }
    __syncthreads();
    if (tid < 16) {
        atomicAdd(&g_ssum[b * NF + tid], red[tid]);
        atomicAdd(&g_ssq [b * NF + tid], red[16 + tid]);
    }
}

// ---------------------------------------------------------------------------
// 7x7 reflect conv, last layer (16 -> 3) + tanh + FUSED instance pooling.
// TWO rows per block, 8 px/thread: tid 0-63 -> row A, 64-127 -> row B.
// 14 loads+norm per ky serve 168 FMA (vs 20 per 168 with 4px threads).
// ---------------------------------------------------------------------------
__global__ __launch_bounds__(128) void conv7_out_k(
    const float* __restrict__ in, const int* __restrict__ ids,
    const float* __restrict__ w, const float* __restrict__ bias)
{
    const int W = WW, H = HH;
    const int tid = threadIdx.x;
    const int b = blockIdx.y;
    const int oy = blockIdx.x * 2 + (tid >> 6);     // 2 rows per block
    const int ox0 = (tid & 63) * 8;                 // 8 px per thread

    __shared__ float ws[NF][49][4];
    __shared__ float p_sum[NUM_IDS * FEAT];
    __shared__ float p_cnt[NUM_IDS];
    for (int e = tid; e < NF * 49 * 4; e += 128) {
        int co = e % 4;
        int tap = (e / 4) % 49;
        int ci = e / (4 * 49);
        ws[ci][tap][co] = (co < FEAT) ? w[(co * NF + ci) * 49 + tap] : 0.f;
    }
    if (tid < NUM_IDS * FEAT) p_sum[tid] = 0.f;
    if (tid < NUM_IDS) p_cnt[tid] = 0.f;
    __syncthreads();

    float acc[8][3];
#pragma unroll
    for (int px = 0; px < 8; px++)
#pragma unroll
        for (int c = 0; c < 3; c++) acc[px][c] = 0.f;

    for (int ci = 0; ci < NF; ci++) {
        const float m = g_mean[b * NF + ci];
        const float s = g_istd[b * NF + ci];
        const float* ip = in + ((size_t)(b * NF + ci)) * H * W;
#pragma unroll
        for (int ky = 0; ky < 7; ky++) {
            int iy = reflect_idx(oy - 3 + ky, H);
            const float* row = ip + (size_t)iy * W;
            float vv[14];
#pragma unroll
            for (int k = 0; k < 14; k++) {
                int ix = reflect_idx(ox0 - 3 + k, W);
                vv[k] = fmaxf((__ldg(row + ix) - m) * s, 0.f);
            }
#pragma unroll
            for (int kx = 0; kx < 7; kx++) {
                const float4 wv = *(const float4*)&ws[ci][ky * 7 + kx][0];
#pragma unroll
                for (int px = 0; px < 8; px++) {
                    const float t = vv[kx + px];
                    acc[px][0] += t * wv.x;
                    acc[px][1] += t * wv.y;
                    acc[px][2] += t * wv.z;
                }
            }
        }
    }

    const int* idrow = ids + (size_t)b * H * W + (size_t)oy * W + ox0;
#pragma unroll
    for (int px = 0; px < 8; px++) {
        int id = idrow[px];
        atomicAdd(&p_cnt[id], 1.f);
#pragma unroll
        for (int c = 0; c < 3; c++) {
            float v = tanhf(acc[px][c] + __ldg(bias + c));
            atomicAdd(&p_sum[id * FEAT + c], v);
        }
    }
    __syncthreads();
    if (tid < NUM_IDS * FEAT) atomicAdd(&g_sums[b * NUM_IDS * FEAT + tid], p_sum[tid]);
    if (tid < NUM_IDS) atomicAdd(&g_cnt[b * NUM_IDS + tid], p_cnt[tid]);
}

// ---------------------------------------------------------------------------
__global__ void prenorm_k(float* __restrict__ x, int HW4, int total4)
{
    int i = blockIdx.x * blockDim.x + threadIdx.x;
    if (i >= total4) return;
    int bc = i / HW4;
    float m = g_mean[bc], s = g_istd[bc];
    float4 v = ((float4*)x)[i];
    v.x = fmaxf((v.x - m) * s, 0.f);
    v.y = fmaxf((v.y - m) * s, 0.f);
    v.z = fmaxf((v.z - m) * s, 0.f);
    v.w = fmaxf((v.w - m) * s, 0.f);
    ((float4*)x)[i] = v;
}

__global__ void stats_final(int n, int HW)
{
    int i = blockIdx.x * blockDim.x + threadIdx.x;
    if (i >= n) return;
    float m = g_ssum[i] / (float)HW;
    float var = g_ssq[i] / (float)HW - m * m;
    g_mean[i] = m;
    g_istd[i] = rsqrtf(var + EPS);
    g_ssum[i] = 0.f;
    g_ssq[i] = 0.f;
}

__global__ void pool_zero()
{
    int i = blockIdx.x * blockDim.x + threadIdx.x;
    if (i < BATCH * NUM_IDS * FEAT) g_sums[i] = 0.f;
    if (i < BATCH * NUM_IDS) g_cnt[i] = 0.f;
}

__global__ void pool_finalize()
{
    int i = blockIdx.x * blockDim.x + threadIdx.x;
    if (i >= BATCH * NUM_IDS) return;
    float c = g_cnt[i];
    float inv = 1.f / fmaxf(c, 1.f);
#pragma unroll
    for (int k = 0; k < FEAT; k++) g_sums[i * FEAT + k] *= inv;
}

__global__ void pool_scatter(const int* __restrict__ ids,
                             float* __restrict__ out, int HW)
{
    int idx = blockIdx.x * blockDim.x + threadIdx.x;
    int total4 = BATCH * HW / 4;
    if (idx >= total4) return;
    int hw4 = HW / 4;
    int bb = idx / hw4;
    int p4 = (idx % hw4) * 4;
    int4 id4 = ((const int4*)(ids + (size_t)bb * HW))[idx % hw4];
    const float* sb = g_sums + bb * NUM_IDS * FEAT;
#pragma unroll
    for (int c = 0; c < FEAT; c++) {
        float4 v;
        v.x = sb[id4.x * FEAT + c];
        v.y = sb[id4.y * FEAT + c];
        v.z = sb[id4.z * FEAT + c];
        v.w = sb[id4.w * FEAT + c];
        *(float4*)(out + ((size_t)bb * FEAT + c) * HW + p4) = v;
    }
}

// ---------------------------------------------------------------------------
extern "C" void kernel_launch(void* const* d_in, const int* in_sizes, int n_in,
                              void* d_out, int out_size)
{
    const float* x     = (const float*)d_in[0];
    const int*   imap  = (const int*)  d_in[1];
    const float* w_in  = (const float*)d_in[2];
    const float* b_in  = (const float*)d_in[3];
    const float* w_d[4], *b_d[4], *w_u[4], *b_u[4];
    for (int i = 0; i < 4; i++) {
        w_d[i] = (const float*)d_in[4 + 2 * i];
        b_d[i] = (const float*)d_in[5 + 2 * i];
        w_u[i] = (const float*)d_in[12 + 2 * i];
        b_u[i] = (const float*)d_in[13 + 2 * i];
    }
    const float* w_out = (const float*)d_in[20];
    const float* b_out = (const float*)d_in[21];
    float* out = (float*)d_out;

    float* A; float* B;
    cudaGetSymbolAddress((void**)&A, g_bufA);
    cudaGetSymbolAddress((void**)&B, g_bufB);

    pool_zero<<<cdiv(BATCH * NUM_IDS * FEAT, 256), 256>>>();

    // 1) in conv
    {
        dim3 grid(HH, BATCH);
        conv7_in_k<<<grid, 128>>>(x, w_in, b_in, A);
        stats_final<<<1, 128>>>(BATCH * NF, HH * WW);
    }

    // 2) down path; i>=2 prenorm
    float* src = A; float* dst = B;
    int C = NF, H = HH, W = WW;
    for (int i = 0; i < 4; i++) {
        int Cout = 2 * C, Ho = H / 2, Wo = W / 2;
        dim3 grid((Ho * Wo) / 256, Cout / CO_T, BATCH);
        int wsh = ilog2(Wo);
        if (i >= 2) {
            int total4 = BATCH * C * H * W / 4;
            prenorm_k<<<cdiv(total4, 256), 256>>>(src, H * W / 4, total4);
            conv3s2_k<false><<<grid, 128>>>(src, w_d[i], b_d[i], dst, C, Cout, H, W, wsh);
        } else {
            conv3s2_k<true><<<grid, 128>>>(src, w_d[i], b_d[i], dst, C, Cout, H, W, wsh);
        }
        stats_final<<<cdiv(BATCH * Cout, 128), 128>>>(BATCH * Cout, Ho * Wo);
        float* t = src; src = dst; dst = t;
        C = Cout; H = Ho; W = Wo;
    }

    // 3) up path; i<=1 prenorm
    for (int i = 0; i < 4; i++) {
        int Cout = C / 2, Ho = 2 * H, Wo = 2 * W;
        dim3 grid((H * W) / 128, Cout / CO_T, BATCH);
        int wsh = ilog2(W);
        if (i <= 1) {
            int total4 = BATCH * C * H * W / 4;
            prenorm_k<<<cdiv(total4, 256), 256>>>(src, H * W / 4, total4);
            tconv3s2_k<false><<<grid, 128>>>(src, w_u[i], b_u[i], dst, C, Cout, H, W, wsh);
        } else {
            tconv3s2_k<true><<<grid, 128>>>(src, w_u[i], b_u[i], dst, C, Cout, H, W, wsh);
        }
        stats_final<<<cdiv(BATCH * Cout, 128), 128>>>(BATCH * Cout, Ho * Wo);
        float* t = src; src = dst; dst = t;
        C = Cout; H = Ho; W = Wo;
    }

    // 4) out conv + tanh + fused pooling (2 rows per block, 8 px/thread)
    {
        dim3 grid(HH / 2, BATCH);
        conv7_out_k<<<grid, 128>>>(src, imap, w_out, b_out);
    }

    // 5) finalize + scatter
    pool_finalize<<<1, 256>>>();
    pool_scatter<<<cdiv(BATCH * HH * WW / 4, 256), 256>>>(imap, out, HH * WW);
}

// round 15
// speedup vs baseline: 1.0421x; 1.0131x over previous
#include <cuda_runtime.h>
#include <math.h>

// ---------------------------------------------------------------------------
#define BATCH   8
#define CIN     3
#define HH      512
#define WW      512
#define NF      16
#define FEAT    3
#define NUM_IDS 32
#define EPS     1e-5f

#define BUF_ELEMS (8*16*512*512)

__device__ float g_bufA[BUF_ELEMS];
__device__ float g_bufB[BUF_ELEMS];
__device__ float g_mean[8*256];
__device__ float g_istd[8*256];
__device__ float g_ssum[8*256];
__device__ float g_ssq [8*256];
__device__ float g_sums[BATCH*NUM_IDS*FEAT];
__device__ float g_cnt [BATCH*NUM_IDS];

static inline int cdiv(int a, int b) { return (a + b - 1) / b; }
static inline int ilog2(int v) { int r = 0; while ((1 << r) < v) r++; return r; }

#define CO_T 16
#define CI_CHUNK 16

__device__ __forceinline__ float warp_sum(float v) {
    v += __shfl_down_sync(0xffffffffu, v, 16);
    v += __shfl_down_sync(0xffffffffu, v, 8);
    v += __shfl_down_sync(0xffffffffu, v, 4);
    v += __shfl_down_sync(0xffffffffu, v, 2);
    v += __shfl_down_sync(0xffffffffu, v, 1);
    return v;
}

__device__ __forceinline__ int reflect_idx(int i, int n) {
    return (i < 0) ? -i : ((i >= n) ? 2 * n - 2 - i : i);
}

// ---------------------------------------------------------------------------
// conv 3x3 stride 2 pad 1. 16 output channels/thread, 2 same-row pixels.
// ROW-STREAMED input: 3 aligned float2 loads per row, consumed immediately.
// Exact grid; shift/mask; float2 stores; stats fused.  (R11 verified config)
// ---------------------------------------------------------------------------
template<bool NORM>
__global__ __launch_bounds__(128) void conv3s2_k(
    const float* __restrict__ in, const float* __restrict__ w,
    const float* __restrict__ bias, float* __restrict__ out,
    int Cin, int Cout, int Hin, int Win, int wshift)
{
    const int Hout = Hin >> 1, Wout = Win >> 1;
    const int HWo = Hout * Wout;
    const size_t HWi = (size_t)Hin * Win;
    const int tid = threadIdx.x;
    const int b = blockIdx.z;
    const int co0 = blockIdx.y * CO_T;
    const int p0 = blockIdx.x * 256 + tid * 2;         // exact grid
    const int oy = p0 >> wshift;
    const int ox = p0 & (Wout - 1);
    const bool py = oy > 0;
    const bool pxl = ox > 0;

    float acc[2][CO_T];
#pragma unroll
    for (int px = 0; px < 2; px++)
#pragma unroll
        for (int c = 0; c < CO_T; c++) acc[px][c] = 0.f;

    __shared__ float ws[CI_CHUNK][9][CO_T];
    __shared__ float sm_m[CI_CHUNK], sm_s[CI_CHUNK];
    __shared__ float red[2 * CO_T];

    // base: row 2oy-1, col 2ox-2 (8B aligned)
    const float* base0 = in + (size_t)(b * Cin) * HWi +
                         ((size_t)(2 * oy - 1)) * Win + (2 * ox - 2);
    const float2 z2 = make_float2(0.f, 0.f);

    for (int cb = 0; cb < Cin; cb += CI_CHUNK) {
        for (int e = tid; e < CI_CHUNK * 9 * CO_T; e += 128) {
            int co = e % CO_T;
            int tap = (e / CO_T) % 9;
            int ci = e / (CO_T * 9);
            ws[ci][tap][co] = w[((co0 + co) * Cin + cb + ci) * 9 + tap];
        }
        if (NORM && tid < CI_CHUNK) {
            sm_m[tid] = g_mean[b * Cin + cb + tid];
            sm_s[tid] = g_istd[b * Cin + cb + tid];
        }
        __syncthreads();

        const float* rp = base0 + (size_t)cb * HWi;
        for (int ci = 0; ci < CI_CHUNK; ci++, rp += HWi) {
            float m = 0.f, s = 1.f;
            if (NORM) { m = sm_m[ci]; s = sm_s[ci]; }
#pragma unroll
            for (int r = 0; r < 3; r++) {
                const float2* q = (const float2*)(rp + r * Win);
                bool rowok = (r > 0) || py;
                float2 av = (rowok && pxl) ? __ldg(q)     : z2;
                float2 bv = rowok          ? __ldg(q + 1) : z2;
                float2 cv = rowok          ? __ldg(q + 2) : z2;
                float v[5];
                v[0] = av.y; v[1] = bv.x; v[2] = bv.y; v[3] = cv.x; v[4] = cv.y;
                if (NORM) {
#pragma unroll
                    for (int j = 0; j < 5; j++)
                        v[j] = fmaxf((v[j] - m) * s, 0.f);
                    if (!rowok) { v[0] = v[1] = v[2] = v[3] = v[4] = 0.f; }
                    if (!pxl) v[0] = 0.f;
                }
#pragma unroll
                for (int kx = 0; kx < 3; kx++) {
                    const float4 w0 = *(const float4*)&ws[ci][r * 3 + kx][0];
                    const float4 w1 = *(const float4*)&ws[ci][r * 3 + kx][4];
                    const float4 w2 = *(const float4*)&ws[ci][r * 3 + kx][8];
                    const float4 w3 = *(const float4*)&ws[ci][r * 3 + kx][12];
                    const float t0 = v[kx];
                    const float t1 = v[kx + 2];
                    acc[0][0]  += t0 * w0.x; acc[0][1]  += t0 * w0.y;
                    acc[0][2]  += t0 * w0.z; acc[0][3]  += t0 * w0.w;
                    acc[0][4]  += t0 * w1.x; acc[0][5]  += t0 * w1.y;
                    acc[0][6]  += t0 * w1.z; acc[0][7]  += t0 * w1.w;
                    acc[0][8]  += t0 * w2.x; acc[0][9]  += t0 * w2.y;
                    acc[0][10] += t0 * w2.z; acc[0][11] += t0 * w2.w;
                    acc[0][12] += t0 * w3.x; acc[0][13] += t0 * w3.y;
                    acc[0][14] += t0 * w3.z; acc[0][15] += t0 * w3.w;
                    acc[1][0]  += t1 * w0.x; acc[1][1]  += t1 * w0.y;
                    acc[1][2]  += t1 * w0.z; acc[1][3]  += t1 * w0.w;
                    acc[1][4]  += t1 * w1.x; acc[1][5]  += t1 * w1.y;
                    acc[1][6]  += t1 * w1.z; acc[1][7]  += t1 * w1.w;
                    acc[1][8]  += t1 * w2.x; acc[1][9]  += t1 * w2.y;
                    acc[1][10] += t1 * w2.z; acc[1][11] += t1 * w2.w;
                    acc[1][12] += t1 * w3.x; acc[1][13] += t1 * w3.y;
                    acc[1][14] += t1 * w3.z; acc[1][15] += t1 * w3.w;
                }
            }
        }
        __syncthreads();
    }

    if (tid < 2 * CO_T) red[tid] = 0.f;
    __syncthreads();

    const int lane = tid & 31;
    const size_t obase = ((size_t)(b * Cout + co0)) * HWo;
#pragma unroll
    for (int co = 0; co < CO_T; co++) {
        float bv = __ldg(bias + co0 + co);
        float v0 = acc[0][co] + bv;
        float v1 = acc[1][co] + bv;
        *(float2*)(out + obase + (size_t)co * HWo + p0) = make_float2(v0, v1);
        float s = warp_sum(v0 + v1);
        float q = warp_sum(v0 * v0 + v1 * v1);
        if (lane == 0) {
            atomicAdd(&red[co], s);
            atomicAdd(&red[CO_T + co], q);
        }
    }
    __syncthreads();
    if (tid < CO_T) {
        atomicAdd(&g_ssum[b * Cout + co0 + tid], red[tid]);
        atomicAdd(&g_ssq [b * Cout + co0 + tid], red[CO_T + tid]);
    }
}

// ---------------------------------------------------------------------------
// ConvTranspose2d k=3 s=2 p=1 op=1, parity-decomposed 2x2 quad per thread.
// Output stored as 2 aligned float2 per channel. CI_CHUNK=16, CO_T=16.
// ---------------------------------------------------------------------------
template<bool NORM>
__global__ __launch_bounds__(128) void tconv3s2_k(
    const float* __restrict__ in, const float* __restrict__ w,
    const float* __restrict__ bias, float* __restrict__ out,
    int Cin, int Cout, int Hin, int Win, int wshift)
{
    const size_t HWi = (size_t)Hin * Win;
    const int q = blockIdx.x * blockDim.x + threadIdx.x;
    const int b = blockIdx.z;
    const int co0 = blockIdx.y * CO_T;
    const int m = q >> wshift;
    const int n = q & (Win - 1);
    const bool hx = (n + 1) < Win;
    const bool hy = (m + 1) < Hin;

    float acc[4][CO_T];
#pragma unroll
    for (int p = 0; p < 4; p++)
#pragma unroll
        for (int c = 0; c < CO_T; c++) acc[p][c] = 0.f;

    __shared__ float ws[CI_CHUNK][9][CO_T];
    __shared__ float sm_m[CI_CHUNK], sm_s[CI_CHUNK];
    __shared__ float red[2 * CO_T];

    const float* base0 = in + (size_t)(b * Cin) * HWi + (size_t)m * Win + n;

    for (int cb = 0; cb < Cin; cb += CI_CHUNK) {
        for (int e = threadIdx.x; e < CI_CHUNK * 9 * CO_T; e += 128) {
            int co = e % CO_T;
            int tap = (e / CO_T) % 9;
            int ci = e / (CO_T * 9);
            ws[ci][tap][co] = w[((size_t)(cb + ci) * Cout + co0 + co) * 9 + tap];
        }
        if (NORM && threadIdx.x < CI_CHUNK) {
            sm_m[threadIdx.x] = g_mean[b * Cin + cb + threadIdx.x];
            sm_s[threadIdx.x] = g_istd[b * Cin + cb + threadIdx.x];
        }
        __syncthreads();

        const float* r0 = base0 + (size_t)cb * HWi;
        for (int ci = 0; ci < CI_CHUNK; ci++, r0 += HWi) {
            float mm = 0.f, sc = 1.f;
            if (NORM) { mm = sm_m[ci]; sc = sm_s[ci]; }
            float v00 = __ldg(r0);
            float v01 = hx ? __ldg(r0 + 1) : 0.f;
            float v10 = hy ? __ldg(r0 + Win) : 0.f;
            float v11 = (hx && hy) ? __ldg(r0 + Win + 1) : 0.f;
            if (NORM) {
                v00 = fmaxf((v00 - mm) * sc, 0.f);
                v01 = fmaxf((v01 - mm) * sc, 0.f);
                v10 = fmaxf((v10 - mm) * sc, 0.f);
                v11 = fmaxf((v11 - mm) * sc, 0.f);
                if (!hx) { v01 = 0.f; v11 = 0.f; }
                if (!hy) { v10 = 0.f; v11 = 0.f; }
            }
            const float vals[9] = {v00, v01, v00, v10, v00, v11, v10, v01, v00};
            const int taps[9]  = {4, 3, 5, 1, 7, 0, 2, 6, 8};
            const int quads[9] = {0, 1, 1, 2, 2, 3, 3, 3, 3};
#pragma unroll
            for (int k = 0; k < 9; k++) {
                const float4 w0 = *(const float4*)&ws[ci][taps[k]][0];
                const float4 w1 = *(const float4*)&ws[ci][taps[k]][4];
                const float4 w2 = *(const float4*)&ws[ci][taps[k]][8];
                const float4 w3 = *(const float4*)&ws[ci][taps[k]][12];
                const float t = vals[k];
                float* a = acc[quads[k]];
                a[0]  += t * w0.x; a[1]  += t * w0.y; a[2]  += t * w0.z; a[3]  += t * w0.w;
                a[4]  += t * w1.x; a[5]  += t * w1.y; a[6]  += t * w1.z; a[7]  += t * w1.w;
                a[8]  += t * w2.x; a[9]  += t * w2.y; a[10] += t * w2.z; a[11] += t * w2.w;
                a[12] += t * w3.x; a[13] += t * w3.y; a[14] += t * w3.z; a[15] += t * w3.w;
            }
        }
        __syncthreads();
    }

    if (threadIdx.x < 2 * CO_T) red[threadIdx.x] = 0.f;
    __syncthreads();

    const int Hout = 2 * Hin, Wout = 2 * Win;
    const int lane = threadIdx.x & 31;
#pragma unroll
    for (int co = 0; co < CO_T; co++) {
        float bv = __ldg(bias + co0 + co);
        float o0 = acc[0][co] + bv, o1 = acc[1][co] + bv;
        float o2 = acc[2][co] + bv, o3 = acc[3][co] + bv;
        size_t base = ((size_t)(b * Cout + co0 + co)) * Hout * Wout;
        size_t p00 = base + (size_t)(2 * m) * Wout + 2 * n;   // even -> aligned
        *(float2*)(out + p00)        = make_float2(o0, o1);
        *(float2*)(out + p00 + Wout) = make_float2(o2, o3);
        float s = warp_sum(o0 + o1 + o2 + o3);
        float qq = warp_sum(o0 * o0 + o1 * o1 + o2 * o2 + o3 * o3);
        if (lane == 0) {
            atomicAdd(&red[co], s);
            atomicAdd(&red[CO_T + co], qq);
        }
    }
    __syncthreads();
    if (threadIdx.x < CO_T) {
        atomicAdd(&g_ssum[b * Cout + co0 + threadIdx.x], red[threadIdx.x]);
        atomicAdd(&g_ssq [b * Cout + co0 + threadIdx.x], red[CO_T + threadIdx.x]);
    }
}

// ---------------------------------------------------------------------------
// 7x7 reflect conv, first layer (3 -> 16), raw input. One row per block,
// 4 px/thread, all 16 channels. Stats fused.
// ---------------------------------------------------------------------------
__global__ __launch_bounds__(128) void conv7_in_k(
    const float* __restrict__ in, const float* __restrict__ w,
    const float* __restrict__ bias, float* __restrict__ out)
{
    const int W = WW, H = HH;
    const int tid = threadIdx.x;
    const int b = blockIdx.y;
    const int oy = blockIdx.x;
    const int ox0 = tid * 4;

    __shared__ float ws[CIN][49][16];
    __shared__ float red[32];
    for (int e = tid; e < CIN * 49 * 16; e += 128) {
        int co = e % 16;
        int tap = (e / 16) % 49;
        int ci = e / (16 * 49);
        ws[ci][tap][co] = w[(co * CIN + ci) * 49 + tap];
    }
    __syncthreads();

    float acc[4][16];
#pragma unroll
    for (int px = 0; px < 4; px++)
#pragma unroll
        for (int c = 0; c < 16; c++) acc[px][c] = 0.f;

    for (int ci = 0; ci < CIN; ci++) {
        const float* ip = in + ((size_t)(b * CIN + ci)) * H * W;
#pragma unroll
        for (int ky = 0; ky < 7; ky++) {
            int iy = reflect_idx(oy - 3 + ky, H);
            const float* row = ip + (size_t)iy * W;
            float vv[10];
#pragma unroll
            for (int k = 0; k < 10; k++) {
                int ix = reflect_idx(ox0 - 3 + k, W);
                vv[k] = __ldg(row + ix);
            }
#pragma unroll
            for (int kx = 0; kx < 7; kx++) {
                const float4 w0 = *(const float4*)&ws[ci][ky * 7 + kx][0];
                const float4 w1 = *(const float4*)&ws[ci][ky * 7 + kx][4];
                const float4 w2 = *(const float4*)&ws[ci][ky * 7 + kx][8];
                const float4 w3 = *(const float4*)&ws[ci][ky * 7 + kx][12];
#pragma unroll
                for (int px = 0; px < 4; px++) {
                    const float t = vv[kx + px];
                    acc[px][0]  += t * w0.x; acc[px][1]  += t * w0.y;
                    acc[px][2]  += t * w0.z; acc[px][3]  += t * w0.w;
                    acc[px][4]  += t * w1.x; acc[px][5]  += t * w1.y;
                    acc[px][6]  += t * w1.z; acc[px][7]  += t * w1.w;
                    acc[px][8]  += t * w2.x; acc[px][9]  += t * w2.y;
                    acc[px][10] += t * w2.z; acc[px][11] += t * w2.w;
                    acc[px][12] += t * w3.x; acc[px][13] += t * w3.y;
                    acc[px][14] += t * w3.z; acc[px][15] += t * w3.w;
                }
            }
        }
    }

    if (tid < 32) red[tid] = 0.f;
    __syncthreads();

    const int lane = tid & 31;
#pragma unroll
    for (int co = 0; co < 16; co++) {
        float bv = __ldg(bias + co);
        float v0 = acc[0][co] + bv, v1 = acc[1][co] + bv;
        float v2 = acc[2][co] + bv, v3 = acc[3][co] + bv;
        size_t base = ((size_t)(b * NF + co)) * H * W + (size_t)oy * W + ox0;
        *(float4*)(out + base) = make_float4(v0, v1, v2, v3);
        float s = warp_sum(v0 + v1 + v2 + v3);
        float q = warp_sum(v0 * v0 + v1 * v1 + v2 * v2 + v3 * v3);
        if (lane == 0) {
            atomicAdd(&red[co], s);
            atomicAdd(&red[16 + co], q);
        }
    }
    __syncthreads();
    if (tid < 16) {
        atomicAdd(&g_ssum[b * NF + tid], red[tid]);
        atomicAdd(&g_ssq [b * NF + tid], red[16 + tid]);
    }
}

// ---------------------------------------------------------------------------
// 7x7 reflect conv, last layer (16 -> 3) + tanh + FUSED instance pooling.
// One row per block, 4 px/thread.  (R11 verified config)
// ---------------------------------------------------------------------------
__global__ __launch_bounds__(128) void conv7_out_k(
    const float* __restrict__ in, const int* __restrict__ ids,
    const float* __restrict__ w, const float* __restrict__ bias)
{
    const int W = WW, H = HH;
    const int tid = threadIdx.x;
    const int b = blockIdx.y;
    const int oy = blockIdx.x;
    const int ox0 = tid * 4;

    __shared__ float ws[NF][49][4];
    __shared__ float p_sum[NUM_IDS * FEAT];
    __shared__ float p_cnt[NUM_IDS];
    for (int e = tid; e < NF * 49 * 4; e += 128) {
        int co = e % 4;
        int tap = (e / 4) % 49;
        int ci = e / (4 * 49);
        ws[ci][tap][co] = (co < FEAT) ? w[(co * NF + ci) * 49 + tap] : 0.f;
    }
    if (tid < NUM_IDS * FEAT) p_sum[tid] = 0.f;
    if (tid < NUM_IDS) p_cnt[tid] = 0.f;
    __syncthreads();

    float acc[4][3];
#pragma unroll
    for (int px = 0; px < 4; px++)
#pragma unroll
        for (int c = 0; c < 3; c++) acc[px][c] = 0.f;

    for (int ci = 0; ci < NF; ci++) {
        const float m = g_mean[b * NF + ci];
        const float s = g_istd[b * NF + ci];
        const float* ip = in + ((size_t)(b * NF + ci)) * H * W;
#pragma unroll
        for (int ky = 0; ky < 7; ky++) {
            int iy = reflect_idx(oy - 3 + ky, H);
            const float* row = ip + (size_t)iy * W;
            float vv[10];
#pragma unroll
            for (int k = 0; k < 10; k++) {
                int ix = reflect_idx(ox0 - 3 + k, W);
                vv[k] = fmaxf((__ldg(row + ix) - m) * s, 0.f);
            }
#pragma unroll
            for (int kx = 0; kx < 7; kx++) {
                const float4 wv = *(const float4*)&ws[ci][ky * 7 + kx][0];
#pragma unroll
                for (int px = 0; px < 4; px++) {
                    const float t = vv[kx + px];
                    acc[px][0] += t * wv.x;
                    acc[px][1] += t * wv.y;
                    acc[px][2] += t * wv.z;
                }
            }
        }
    }

    const int* idrow = ids + (size_t)b * H * W + (size_t)oy * W + ox0;
#pragma unroll
    for (int px = 0; px < 4; px++) {
        int id = idrow[px];
        atomicAdd(&p_cnt[id], 1.f);
#pragma unroll
        for (int c = 0; c < 3; c++) {
            float v = tanhf(acc[px][c] + __ldg(bias + c));
            atomicAdd(&p_sum[id * FEAT + c], v);
        }
    }
    __syncthreads();
    if (tid < NUM_IDS * FEAT) atomicAdd(&g_sums[b * NUM_IDS * FEAT + tid], p_sum[tid]);
    if (tid < NUM_IDS) atomicAdd(&g_cnt[b * NUM_IDS + tid], p_cnt[tid]);
}

// ---------------------------------------------------------------------------
__global__ void prenorm_k(float* __restrict__ x, int HW4, int total4)
{
    int i = blockIdx.x * blockDim.x + threadIdx.x;
    if (i >= total4) return;
    int bc = i / HW4;
    float m = g_mean[bc], s = g_istd[bc];
    float4 v = ((float4*)x)[i];
    v.x = fmaxf((v.x - m) * s, 0.f);
    v.y = fmaxf((v.y - m) * s, 0.f);
    v.z = fmaxf((v.z - m) * s, 0.f);
    v.w = fmaxf((v.w - m) * s, 0.f);
    ((float4*)x)[i] = v;
}

__global__ void stats_final(int n, int HW)
{
    int i = blockIdx.x * blockDim.x + threadIdx.x;
    if (i >= n) return;
    float m = g_ssum[i] / (float)HW;
    float var = g_ssq[i] / (float)HW - m * m;
    g_mean[i] = m;
    g_istd[i] = rsqrtf(var + EPS);
    g_ssum[i] = 0.f;
    g_ssq[i] = 0.f;
}

__global__ void pool_zero()
{
    int i = blockIdx.x * blockDim.x + threadIdx.x;
    if (i < BATCH * NUM_IDS * FEAT) g_sums[i] = 0.f;
    if (i < BATCH * NUM_IDS) g_cnt[i] = 0.f;
}

__global__ void pool_finalize()
{
    int i = blockIdx.x * blockDim.x + threadIdx.x;
    if (i >= BATCH * NUM_IDS) return;
    float c = g_cnt[i];
    float inv = 1.f / fmaxf(c, 1.f);
#pragma unroll
    for (int k = 0; k < FEAT; k++) g_sums[i * FEAT + k] *= inv;
}

__global__ void pool_scatter(const int* __restrict__ ids,
                             float* __restrict__ out, int HW)
{
    int idx = blockIdx.x * blockDim.x + threadIdx.x;
    int total4 = BATCH * HW / 4;
    if (idx >= total4) return;
    int hw4 = HW / 4;
    int bb = idx / hw4;
    int p4 = (idx % hw4) * 4;
    int4 id4 = ((const int4*)(ids + (size_t)bb * HW))[idx % hw4];
    const float* sb = g_sums + bb * NUM_IDS * FEAT;
#pragma unroll
    for (int c = 0; c < FEAT; c++) {
        float4 v;
        v.x = sb[id4.x * FEAT + c];
        v.y = sb[id4.y * FEAT + c];
        v.z = sb[id4.z * FEAT + c];
        v.w = sb[id4.w * FEAT + c];
        *(float4*)(out + ((size_t)bb * FEAT + c) * HW + p4) = v;
    }
}

// ---------------------------------------------------------------------------
extern "C" void kernel_launch(void* const* d_in, const int* in_sizes, int n_in,
                              void* d_out, int out_size)
{
    const float* x     = (const float*)d_in[0];
    const int*   imap  = (const int*)  d_in[1];
    const float* w_in  = (const float*)d_in[2];
    const float* b_in  = (const float*)d_in[3];
    const float* w_d[4], *b_d[4], *w_u[4], *b_u[4];
    for (int i = 0; i < 4; i++) {
        w_d[i] = (const float*)d_in[4 + 2 * i];
        b_d[i] = (const float*)d_in[5 + 2 * i];
        w_u[i] = (const float*)d_in[12 + 2 * i];
        b_u[i] = (const float*)d_in[13 + 2 * i];
    }
    const float* w_out = (const float*)d_in[20];
    const float* b_out = (const float*)d_in[21];
    float* out = (float*)d_out;

    float* A; float* B;
    cudaGetSymbolAddress((void**)&A, g_bufA);
    cudaGetSymbolAddress((void**)&B, g_bufB);

    pool_zero<<<cdiv(BATCH * NUM_IDS * FEAT, 256), 256>>>();

    // 1) in conv
    {
        dim3 grid(HH, BATCH);
        conv7_in_k<<<grid, 128>>>(x, w_in, b_in, A);
        stats_final<<<1, 128>>>(BATCH * NF, HH * WW);
    }

    // 2) down path — all layers use fused norm-on-load (prenorm passes for
    //    d2/d3 cost more in HBM traffic than the 4% conv saving).
    float* src = A; float* dst = B;
    int C = NF, H = HH, W = WW;
    for (int i = 0; i < 4; i++) {
        int Cout = 2 * C, Ho = H / 2, Wo = W / 2;
        dim3 grid((Ho * Wo) / 256, Cout / CO_T, BATCH);
        int wsh = ilog2(Wo);
        conv3s2_k<true><<<grid, 128>>>(src, w_d[i], b_d[i], dst, C, Cout, H, W, wsh);
        stats_final<<<cdiv(BATCH * Cout, 128), 128>>>(BATCH * Cout, Ho * Wo);
        float* t = src; src = dst; dst = t;
        C = Cout; H = Ho; W = Wo;
    }

    // 3) up path — prenorm only u0 (tiny tensor, reuse 16, Cin=256 loop)
    for (int i = 0; i < 4; i++) {
        int Cout = C / 2, Ho = 2 * H, Wo = 2 * W;
        dim3 grid((H * W) / 128, Cout / CO_T, BATCH);
        int wsh = ilog2(W);
        if (i == 0) {
            int total4 = BATCH * C * H * W / 4;
            prenorm_k<<<cdiv(total4, 256), 256>>>(src, H * W / 4, total4);
            tconv3s2_k<false><<<grid, 128>>>(src, w_u[i], b_u[i], dst, C, Cout, H, W, wsh);
        } else {
            tconv3s2_k<true><<<grid, 128>>>(src, w_u[i], b_u[i], dst, C, Cout, H, W, wsh);
        }
        stats_final<<<cdiv(BATCH * Cout, 128), 128>>>(BATCH * Cout, Ho * Wo);
        float* t = src; src = dst; dst = t;
        C = Cout; H = Ho; W = Wo;
    }

    // 4) out conv + tanh + fused pooling
    {
        dim3 grid(HH, BATCH);
        conv7_out_k<<<grid, 128>>>(src, imap, w_out, b_out);
    }

    // 5) finalize + scatter
    pool_finalize<<<1, 256>>>();
    pool_scatter<<<cdiv(BATCH * HH * WW / 4, 256), 256>>>(imap, out, HH * WW);
}

// round 16
// speedup vs baseline: 1.0522x; 1.0097x over previous
#include <cuda_runtime.h>
#include <math.h>

// ---------------------------------------------------------------------------
#define BATCH   8
#define CIN     3
#define HH      512
#define WW      512
#define NF      16
#define FEAT    3
#define NUM_IDS 32
#define EPS     1e-5f

#define BUF_ELEMS (8*16*512*512)

__device__ float g_bufA[BUF_ELEMS];
__device__ float g_bufB[BUF_ELEMS];
__device__ float g_mean[8*256];
__device__ float g_istd[8*256];
__device__ float g_ssum[8*256];
__device__ float g_ssq [8*256];
__device__ float g_sums[BATCH*NUM_IDS*FEAT];
__device__ float g_cnt [BATCH*NUM_IDS];

static inline int cdiv(int a, int b) { return (a + b - 1) / b; }
static inline int ilog2(int v) { int r = 0; while ((1 << r) < v) r++; return r; }

#define CO_T 16
#define CI_CHUNK 16

__device__ __forceinline__ float warp_sum(float v) {
    v += __shfl_down_sync(0xffffffffu, v, 16);
    v += __shfl_down_sync(0xffffffffu, v, 8);
    v += __shfl_down_sync(0xffffffffu, v, 4);
    v += __shfl_down_sync(0xffffffffu, v, 2);
    v += __shfl_down_sync(0xffffffffu, v, 1);
    return v;
}

__device__ __forceinline__ int reflect_idx(int i, int n) {
    return (i < 0) ? -i : ((i >= n) ? 2 * n - 2 - i : i);
}

// ---------------------------------------------------------------------------
// conv 3x3 stride 2 pad 1. 16 output channels/thread, 2 same-row pixels.
// ROW-STREAMED input: 3 aligned float2 loads per row, consumed immediately.
// Exact grid; shift/mask; float2 stores; stats fused.  (R11 verified config)
// ---------------------------------------------------------------------------
template<bool NORM>
__global__ __launch_bounds__(128) void conv3s2_k(
    const float* __restrict__ in, const float* __restrict__ w,
    const float* __restrict__ bias, float* __restrict__ out,
    int Cin, int Cout, int Hin, int Win, int wshift)
{
    const int Hout = Hin >> 1, Wout = Win >> 1;
    const int HWo = Hout * Wout;
    const size_t HWi = (size_t)Hin * Win;
    const int tid = threadIdx.x;
    const int b = blockIdx.z;
    const int co0 = blockIdx.y * CO_T;
    const int p0 = blockIdx.x * 256 + tid * 2;         // exact grid
    const int oy = p0 >> wshift;
    const int ox = p0 & (Wout - 1);
    const bool py = oy > 0;
    const bool pxl = ox > 0;

    float acc[2][CO_T];
#pragma unroll
    for (int px = 0; px < 2; px++)
#pragma unroll
        for (int c = 0; c < CO_T; c++) acc[px][c] = 0.f;

    __shared__ float ws[CI_CHUNK][9][CO_T];
    __shared__ float sm_m[CI_CHUNK], sm_s[CI_CHUNK];
    __shared__ float red[2 * CO_T];

    // base: row 2oy-1, col 2ox-2 (8B aligned)
    const float* base0 = in + (size_t)(b * Cin) * HWi +
                         ((size_t)(2 * oy - 1)) * Win + (2 * ox - 2);
    const float2 z2 = make_float2(0.f, 0.f);

    for (int cb = 0; cb < Cin; cb += CI_CHUNK) {
        for (int e = tid; e < CI_CHUNK * 9 * CO_T; e += 128) {
            int co = e % CO_T;
            int tap = (e / CO_T) % 9;
            int ci = e / (CO_T * 9);
            ws[ci][tap][co] = w[((co0 + co) * Cin + cb + ci) * 9 + tap];
        }
        if (NORM && tid < CI_CHUNK) {
            sm_m[tid] = g_mean[b * Cin + cb + tid];
            sm_s[tid] = g_istd[b * Cin + cb + tid];
        }
        __syncthreads();

        const float* rp = base0 + (size_t)cb * HWi;
        for (int ci = 0; ci < CI_CHUNK; ci++, rp += HWi) {
            float m = 0.f, s = 1.f;
            if (NORM) { m = sm_m[ci]; s = sm_s[ci]; }
#pragma unroll
            for (int r = 0; r < 3; r++) {
                const float2* q = (const float2*)(rp + r * Win);
                bool rowok = (r > 0) || py;
                float2 av = (rowok && pxl) ? __ldg(q)     : z2;
                float2 bv = rowok          ? __ldg(q + 1) : z2;
                float2 cv = rowok          ? __ldg(q + 2) : z2;
                float v[5];
                v[0] = av.y; v[1] = bv.x; v[2] = bv.y; v[3] = cv.x; v[4] = cv.y;
                if (NORM) {
#pragma unroll
                    for (int j = 0; j < 5; j++)
                        v[j] = fmaxf((v[j] - m) * s, 0.f);
                    if (!rowok) { v[0] = v[1] = v[2] = v[3] = v[4] = 0.f; }
                    if (!pxl) v[0] = 0.f;
                }
#pragma unroll
                for (int kx = 0; kx < 3; kx++) {
                    const float4 w0 = *(const float4*)&ws[ci][r * 3 + kx][0];
                    const float4 w1 = *(const float4*)&ws[ci][r * 3 + kx][4];
                    const float4 w2 = *(const float4*)&ws[ci][r * 3 + kx][8];
                    const float4 w3 = *(const float4*)&ws[ci][r * 3 + kx][12];
                    const float t0 = v[kx];
                    const float t1 = v[kx + 2];
                    acc[0][0]  += t0 * w0.x; acc[0][1]  += t0 * w0.y;
                    acc[0][2]  += t0 * w0.z; acc[0][3]  += t0 * w0.w;
                    acc[0][4]  += t0 * w1.x; acc[0][5]  += t0 * w1.y;
                    acc[0][6]  += t0 * w1.z; acc[0][7]  += t0 * w1.w;
                    acc[0][8]  += t0 * w2.x; acc[0][9]  += t0 * w2.y;
                    acc[0][10] += t0 * w2.z; acc[0][11] += t0 * w2.w;
                    acc[0][12] += t0 * w3.x; acc[0][13] += t0 * w3.y;
                    acc[0][14] += t0 * w3.z; acc[0][15] += t0 * w3.w;
                    acc[1][0]  += t1 * w0.x; acc[1][1]  += t1 * w0.y;
                    acc[1][2]  += t1 * w0.z; acc[1][3]  += t1 * w0.w;
                    acc[1][4]  += t1 * w1.x; acc[1][5]  += t1 * w1.y;
                    acc[1][6]  += t1 * w1.z; acc[1][7]  += t1 * w1.w;
                    acc[1][8]  += t1 * w2.x; acc[1][9]  += t1 * w2.y;
                    acc[1][10] += t1 * w2.z; acc[1][11] += t1 * w2.w;
                    acc[1][12] += t1 * w3.x; acc[1][13] += t1 * w3.y;
                    acc[1][14] += t1 * w3.z; acc[1][15] += t1 * w3.w;
                }
            }
        }
        __syncthreads();
    }

    if (tid < 2 * CO_T) red[tid] = 0.f;
    __syncthreads();

    const int lane = tid & 31;
    const size_t obase = ((size_t)(b * Cout + co0)) * HWo;
#pragma unroll
    for (int co = 0; co < CO_T; co++) {
        float bv = __ldg(bias + co0 + co);
        float v0 = acc[0][co] + bv;
        float v1 = acc[1][co] + bv;
        *(float2*)(out + obase + (size_t)co * HWo + p0) = make_float2(v0, v1);
        float s = warp_sum(v0 + v1);
        float q = warp_sum(v0 * v0 + v1 * v1);
        if (lane == 0) {
            atomicAdd(&red[co], s);
            atomicAdd(&red[CO_T + co], q);
        }
    }
    __syncthreads();
    if (tid < CO_T) {
        atomicAdd(&g_ssum[b * Cout + co0 + tid], red[tid]);
        atomicAdd(&g_ssq [b * Cout + co0 + tid], red[CO_T + tid]);
    }
}

// ---------------------------------------------------------------------------
// ConvTranspose2d k=3 s=2 p=1 op=1, parity-decomposed 2x2 quad per thread.
// Output stored as 2 aligned float2 per channel. CI_CHUNK=16, CO_T=16.
// ---------------------------------------------------------------------------
template<bool NORM>
__global__ __launch_bounds__(128) void tconv3s2_k(
    const float* __restrict__ in, const float* __restrict__ w,
    const float* __restrict__ bias, float* __restrict__ out,
    int Cin, int Cout, int Hin, int Win, int wshift)
{
    const size_t HWi = (size_t)Hin * Win;
    const int q = blockIdx.x * blockDim.x + threadIdx.x;
    const int b = blockIdx.z;
    const int co0 = blockIdx.y * CO_T;
    const int m = q >> wshift;
    const int n = q & (Win - 1);
    const bool hx = (n + 1) < Win;
    const bool hy = (m + 1) < Hin;

    float acc[4][CO_T];
#pragma unroll
    for (int p = 0; p < 4; p++)
#pragma unroll
        for (int c = 0; c < CO_T; c++) acc[p][c] = 0.f;

    __shared__ float ws[CI_CHUNK][9][CO_T];
    __shared__ float sm_m[CI_CHUNK], sm_s[CI_CHUNK];
    __shared__ float red[2 * CO_T];

    const float* base0 = in + (size_t)(b * Cin) * HWi + (size_t)m * Win + n;

    for (int cb = 0; cb < Cin; cb += CI_CHUNK) {
        for (int e = threadIdx.x; e < CI_CHUNK * 9 * CO_T; e += 128) {
            int co = e % CO_T;
            int tap = (e / CO_T) % 9;
            int ci = e / (CO_T * 9);
            ws[ci][tap][co] = w[((size_t)(cb + ci) * Cout + co0 + co) * 9 + tap];
        }
        if (NORM && threadIdx.x < CI_CHUNK) {
            sm_m[threadIdx.x] = g_mean[b * Cin + cb + threadIdx.x];
            sm_s[threadIdx.x] = g_istd[b * Cin + cb + threadIdx.x];
        }
        __syncthreads();

        const float* r0 = base0 + (size_t)cb * HWi;
        for (int ci = 0; ci < CI_CHUNK; ci++, r0 += HWi) {
            float mm = 0.f, sc = 1.f;
            if (NORM) { mm = sm_m[ci]; sc = sm_s[ci]; }
            float v00 = __ldg(r0);
            float v01 = hx ? __ldg(r0 + 1) : 0.f;
            float v10 = hy ? __ldg(r0 + Win) : 0.f;
            float v11 = (hx && hy) ? __ldg(r0 + Win + 1) : 0.f;
            if (NORM) {
                v00 = fmaxf((v00 - mm) * sc, 0.f);
                v01 = fmaxf((v01 - mm) * sc, 0.f);
                v10 = fmaxf((v10 - mm) * sc, 0.f);
                v11 = fmaxf((v11 - mm) * sc, 0.f);
                if (!hx) { v01 = 0.f; v11 = 0.f; }
                if (!hy) { v10 = 0.f; v11 = 0.f; }
            }
            const float vals[9] = {v00, v01, v00, v10, v00, v11, v10, v01, v00};
            const int taps[9]  = {4, 3, 5, 1, 7, 0, 2, 6, 8};
            const int quads[9] = {0, 1, 1, 2, 2, 3, 3, 3, 3};
#pragma unroll
            for (int k = 0; k < 9; k++) {
                const float4 w0 = *(const float4*)&ws[ci][taps[k]][0];
                const float4 w1 = *(const float4*)&ws[ci][taps[k]][4];
                const float4 w2 = *(const float4*)&ws[ci][taps[k]][8];
                const float4 w3 = *(const float4*)&ws[ci][taps[k]][12];
                const float t = vals[k];
                float* a = acc[quads[k]];
                a[0]  += t * w0.x; a[1]  += t * w0.y; a[2]  += t * w0.z; a[3]  += t * w0.w;
                a[4]  += t * w1.x; a[5]  += t * w1.y; a[6]  += t * w1.z; a[7]  += t * w1.w;
                a[8]  += t * w2.x; a[9]  += t * w2.y; a[10] += t * w2.z; a[11] += t * w2.w;
                a[12] += t * w3.x; a[13] += t * w3.y; a[14] += t * w3.z; a[15] += t * w3.w;
            }
        }
        __syncthreads();
    }

    if (threadIdx.x < 2 * CO_T) red[threadIdx.x] = 0.f;
    __syncthreads();

    const int Hout = 2 * Hin, Wout = 2 * Win;
    const int lane = threadIdx.x & 31;
#pragma unroll
    for (int co = 0; co < CO_T; co++) {
        float bv = __ldg(bias + co0 + co);
        float o0 = acc[0][co] + bv, o1 = acc[1][co] + bv;
        float o2 = acc[2][co] + bv, o3 = acc[3][co] + bv;
        size_t base = ((size_t)(b * Cout + co0 + co)) * Hout * Wout;
        size_t p00 = base + (size_t)(2 * m) * Wout + 2 * n;   // even -> aligned
        *(float2*)(out + p00)        = make_float2(o0, o1);
        *(float2*)(out + p00 + Wout) = make_float2(o2, o3);
        float s = warp_sum(o0 + o1 + o2 + o3);
        float qq = warp_sum(o0 * o0 + o1 * o1 + o2 * o2 + o3 * o3);
        if (lane == 0) {
            atomicAdd(&red[co], s);
            atomicAdd(&red[CO_T + co], qq);
        }
    }
    __syncthreads();
    if (threadIdx.x < CO_T) {
        atomicAdd(&g_ssum[b * Cout + co0 + threadIdx.x], red[threadIdx.x]);
        atomicAdd(&g_ssq [b * Cout + co0 + threadIdx.x], red[CO_T + threadIdx.x]);
    }
}

// ---------------------------------------------------------------------------
// 7x7 reflect conv, first layer (3 -> 16), raw input. One row per block,
// 4 px/thread, all 16 channels. Reflect indices hoisted. Stats fused.
// ---------------------------------------------------------------------------
__global__ __launch_bounds__(128) void conv7_in_k(
    const float* __restrict__ in, const float* __restrict__ w,
    const float* __restrict__ bias, float* __restrict__ out)
{
    const int W = WW, H = HH;
    const int tid = threadIdx.x;
    const int b = blockIdx.y;
    const int oy = blockIdx.x;
    const int ox0 = tid * 4;

    __shared__ float ws[CIN][49][16];
    __shared__ float red[32];
    for (int e = tid; e < CIN * 49 * 16; e += 128) {
        int co = e % 16;
        int tap = (e / 16) % 49;
        int ci = e / (16 * 49);
        ws[ci][tap][co] = w[(co * CIN + ci) * 49 + tap];
    }
    __syncthreads();

    // hoisted reflect indices (invariant across ci and ky for ixs; across ci for iys)
    int ixs[10];
#pragma unroll
    for (int k = 0; k < 10; k++) ixs[k] = reflect_idx(ox0 - 3 + k, W);
    int iys[7];
#pragma unroll
    for (int k = 0; k < 7; k++) iys[k] = reflect_idx(oy - 3 + k, H);

    float acc[4][16];
#pragma unroll
    for (int px = 0; px < 4; px++)
#pragma unroll
        for (int c = 0; c < 16; c++) acc[px][c] = 0.f;

    for (int ci = 0; ci < CIN; ci++) {
        const float* ip = in + ((size_t)(b * CIN + ci)) * H * W;
#pragma unroll
        for (int ky = 0; ky < 7; ky++) {
            const float* row = ip + (size_t)iys[ky] * W;
            float vv[10];
#pragma unroll
            for (int k = 0; k < 10; k++) vv[k] = __ldg(row + ixs[k]);
#pragma unroll
            for (int kx = 0; kx < 7; kx++) {
                const float4 w0 = *(const float4*)&ws[ci][ky * 7 + kx][0];
                const float4 w1 = *(const float4*)&ws[ci][ky * 7 + kx][4];
                const float4 w2 = *(const float4*)&ws[ci][ky * 7 + kx][8];
                const float4 w3 = *(const float4*)&ws[ci][ky * 7 + kx][12];
#pragma unroll
                for (int px = 0; px < 4; px++) {
                    const float t = vv[kx + px];
                    acc[px][0]  += t * w0.x; acc[px][1]  += t * w0.y;
                    acc[px][2]  += t * w0.z; acc[px][3]  += t * w0.w;
                    acc[px][4]  += t * w1.x; acc[px][5]  += t * w1.y;
                    acc[px][6]  += t * w1.z; acc[px][7]  += t * w1.w;
                    acc[px][8]  += t * w2.x; acc[px][9]  += t * w2.y;
                    acc[px][10] += t * w2.z; acc[px][11] += t * w2.w;
                    acc[px][12] += t * w3.x; acc[px][13] += t * w3.y;
                    acc[px][14] += t * w3.z; acc[px][15] += t * w3.w;
                }
            }
        }
    }

    if (tid < 32) red[tid] = 0.f;
    __syncthreads();

    const int lane = tid & 31;
#pragma unroll
    for (int co = 0; co < 16; co++) {
        float bv = __ldg(bias + co);
        float v0 = acc[0][co] + bv, v1 = acc[1][co] + bv;
        float v2 = acc[2][co] + bv, v3 = acc[3][co] + bv;
        size_t base = ((size_t)(b * NF + co)) * H * W + (size_t)oy * W + ox0;
        *(float4*)(out + base) = make_float4(v0, v1, v2, v3);
        float s = warp_sum(v0 + v1 + v2 + v3);
        float q = warp_sum(v0 * v0 + v1 * v1 + v2 * v2 + v3 * v3);
        if (lane == 0) {
            atomicAdd(&red[co], s);
            atomicAdd(&red[16 + co], q);
        }
    }
    __syncthreads();
    if (tid < 16) {
        atomicAdd(&g_ssum[b * NF + tid], red[tid]);
        atomicAdd(&g_ssq [b * NF + tid], red[16 + tid]);
    }
}

// ---------------------------------------------------------------------------
// 7x7 reflect conv, last layer (16 -> 3) + tanh + FUSED instance pooling.
// One row per block, 4 px/thread. Reflect indices hoisted.
// ---------------------------------------------------------------------------
__global__ __launch_bounds__(128) void conv7_out_k(
    const float* __restrict__ in, const int* __restrict__ ids,
    const float* __restrict__ w, const float* __restrict__ bias)
{
    const int W = WW, H = HH;
    const int tid = threadIdx.x;
    const int b = blockIdx.y;
    const int oy = blockIdx.x;
    const int ox0 = tid * 4;

    __shared__ float ws[NF][49][4];
    __shared__ float p_sum[NUM_IDS * FEAT];
    __shared__ float p_cnt[NUM_IDS];
    for (int e = tid; e < NF * 49 * 4; e += 128) {
        int co = e % 4;
        int tap = (e / 4) % 49;
        int ci = e / (4 * 49);
        ws[ci][tap][co] = (co < FEAT) ? w[(co * NF + ci) * 49 + tap] : 0.f;
    }
    if (tid < NUM_IDS * FEAT) p_sum[tid] = 0.f;
    if (tid < NUM_IDS) p_cnt[tid] = 0.f;
    __syncthreads();

    int ixs[10];
#pragma unroll
    for (int k = 0; k < 10; k++) ixs[k] = reflect_idx(ox0 - 3 + k, W);
    int iys[7];
#pragma unroll
    for (int k = 0; k < 7; k++) iys[k] = reflect_idx(oy - 3 + k, H);

    float acc[4][3];
#pragma unroll
    for (int px = 0; px < 4; px++)
#pragma unroll
        for (int c = 0; c < 3; c++) acc[px][c] = 0.f;

    for (int ci = 0; ci < NF; ci++) {
        const float m = g_mean[b * NF + ci];
        const float s = g_istd[b * NF + ci];
        const float* ip = in + ((size_t)(b * NF + ci)) * H * W;
#pragma unroll
        for (int ky = 0; ky < 7; ky++) {
            const float* row = ip + (size_t)iys[ky] * W;
            float vv[10];
#pragma unroll
            for (int k = 0; k < 10; k++)
                vv[k] = fmaxf((__ldg(row + ixs[k]) - m) * s, 0.f);
#pragma unroll
            for (int kx = 0; kx < 7; kx++) {
                const float4 wv = *(const float4*)&ws[ci][ky * 7 + kx][0];
#pragma unroll
                for (int px = 0; px < 4; px++) {
                    const float t = vv[kx + px];
                    acc[px][0] += t * wv.x;
                    acc[px][1] += t * wv.y;
                    acc[px][2] += t * wv.z;
                }
            }
        }
    }

    const int* idrow = ids + (size_t)b * H * W + (size_t)oy * W + ox0;
#pragma unroll
    for (int px = 0; px < 4; px++) {
        int id = idrow[px];
        atomicAdd(&p_cnt[id], 1.f);
#pragma unroll
        for (int c = 0; c < 3; c++) {
            float v = tanhf(acc[px][c] + __ldg(bias + c));
            atomicAdd(&p_sum[id * FEAT + c], v);
        }
    }
    __syncthreads();
    if (tid < NUM_IDS * FEAT) atomicAdd(&g_sums[b * NUM_IDS * FEAT + tid], p_sum[tid]);
    if (tid < NUM_IDS) atomicAdd(&g_cnt[b * NUM_IDS + tid], p_cnt[tid]);
}

// ---------------------------------------------------------------------------
__global__ void prenorm_k(float* __restrict__ x, int HW4, int total4)
{
    int i = blockIdx.x * blockDim.x + threadIdx.x;
    if (i >= total4) return;
    int bc = i / HW4;
    float m = g_mean[bc], s = g_istd[bc];
    float4 v = ((float4*)x)[i];
    v.x = fmaxf((v.x - m) * s, 0.f);
    v.y = fmaxf((v.y - m) * s, 0.f);
    v.z = fmaxf((v.z - m) * s, 0.f);
    v.w = fmaxf((v.w - m) * s, 0.f);
    ((float4*)x)[i] = v;
}

__global__ void stats_final(int n, int HW)
{
    int i = blockIdx.x * blockDim.x + threadIdx.x;
    if (i >= n) return;
    float m = g_ssum[i] / (float)HW;
    float var = g_ssq[i] / (float)HW - m * m;
    g_mean[i] = m;
    g_istd[i] = rsqrtf(var + EPS);
    g_ssum[i] = 0.f;
    g_ssq[i] = 0.f;
}

__global__ void pool_zero()
{
    int i = blockIdx.x * blockDim.x + threadIdx.x;
    if (i < BATCH * NUM_IDS * FEAT) g_sums[i] = 0.f;
    if (i < BATCH * NUM_IDS) g_cnt[i] = 0.f;
}

__global__ void pool_finalize()
{
    int i = blockIdx.x * blockDim.x + threadIdx.x;
    if (i >= BATCH * NUM_IDS) return;
    float c = g_cnt[i];
    float inv = 1.f / fmaxf(c, 1.f);
#pragma unroll
    for (int k = 0; k < FEAT; k++) g_sums[i * FEAT + k] *= inv;
}

__global__ void pool_scatter(const int* __restrict__ ids,
                             float* __restrict__ out, int HW)
{
    int idx = blockIdx.x * blockDim.x + threadIdx.x;
    int total4 = BATCH * HW / 4;
    if (idx >= total4) return;
    int hw4 = HW / 4;
    int bb = idx / hw4;
    int p4 = (idx % hw4) * 4;
    int4 id4 = ((const int4*)(ids + (size_t)bb * HW))[idx % hw4];
    const float* sb = g_sums + bb * NUM_IDS * FEAT;
#pragma unroll
    for (int c = 0; c < FEAT; c++) {
        float4 v;
        v.x = sb[id4.x * FEAT + c];
        v.y = sb[id4.y * FEAT + c];
        v.z = sb[id4.z * FEAT + c];
        v.w = sb[id4.w * FEAT + c];
        *(float4*)(out + ((size_t)bb * FEAT + c) * HW + p4) = v;
    }
}

// ---------------------------------------------------------------------------
extern "C" void kernel_launch(void* const* d_in, const int* in_sizes, int n_in,
                              void* d_out, int out_size)
{
    const float* x     = (const float*)d_in[0];
    const int*   imap  = (const int*)  d_in[1];
    const float* w_in  = (const float*)d_in[2];
    const float* b_in  = (const float*)d_in[3];
    const float* w_d[4], *b_d[4], *w_u[4], *b_u[4];
    for (int i = 0; i < 4; i++) {
        w_d[i] = (const float*)d_in[4 + 2 * i];
        b_d[i] = (const float*)d_in[5 + 2 * i];
        w_u[i] = (const float*)d_in[12 + 2 * i];
        b_u[i] = (const float*)d_in[13 + 2 * i];
    }
    const float* w_out = (const float*)d_in[20];
    const float* b_out = (const float*)d_in[21];
    float* out = (float*)d_out;

    float* A; float* B;
    cudaGetSymbolAddress((void**)&A, g_bufA);
    cudaGetSymbolAddress((void**)&B, g_bufB);

    pool_zero<<<cdiv(BATCH * NUM_IDS * FEAT, 256), 256>>>();

    // 1) in conv
    {
        dim3 grid(HH, BATCH);
        conv7_in_k<<<grid, 128>>>(x, w_in, b_in, A);
        stats_final<<<1, 128>>>(BATCH * NF, HH * WW);
    }

    // 2) down path; i>=2 prenorm (R11 verified configuration)
    float* src = A; float* dst = B;
    int C = NF, H = HH, W = WW;
    for (int i = 0; i < 4; i++) {
        int Cout = 2 * C, Ho = H / 2, Wo = W / 2;
        dim3 grid((Ho * Wo) / 256, Cout / CO_T, BATCH);
        int wsh = ilog2(Wo);
        if (i >= 2) {
            int total4 = BATCH * C * H * W / 4;
            prenorm_k<<<cdiv(total4, 256), 256>>>(src, H * W / 4, total4);
            conv3s2_k<false><<<grid, 128>>>(src, w_d[i], b_d[i], dst, C, Cout, H, W, wsh);
        } else {
            conv3s2_k<true><<<grid, 128>>>(src, w_d[i], b_d[i], dst, C, Cout, H, W, wsh);
        }
        stats_final<<<cdiv(BATCH * Cout, 128), 128>>>(BATCH * Cout, Ho * Wo);
        float* t = src; src = dst; dst = t;
        C = Cout; H = Ho; W = Wo;
    }

    // 3) up path; i<=1 prenorm (R11 verified configuration)
    for (int i = 0; i < 4; i++) {
        int Cout = C / 2, Ho = 2 * H, Wo = 2 * W;
        dim3 grid((H * W) / 128, Cout / CO_T, BATCH);
        int wsh = ilog2(W);
        if (i <= 1) {
            int total4 = BATCH * C * H * W / 4;
            prenorm_k<<<cdiv(total4, 256), 256>>>(src, H * W / 4, total4);
            tconv3s2_k<false><<<grid, 128>>>(src, w_u[i], b_u[i], dst, C, Cout, H, W, wsh);
        } else {
            tconv3s2_k<true><<<grid, 128>>>(src, w_u[i], b_u[i], dst, C, Cout, H, W, wsh);
        }
        stats_final<<<cdiv(BATCH * Cout, 128), 128>>>(BATCH * Cout, Ho * Wo);
        float* t = src; src = dst; dst = t;
        C = Cout; H = Ho; W = Wo;
    }

    // 4) out conv + tanh + fused pooling
    {
        dim3 grid(HH, BATCH);
        conv7_out_k<<<grid, 128>>>(src, imap, w_out, b_out);
    }

    // 5) finalize + scatter
    pool_finalize<<<1, 256>>>();
    pool_scatter<<<cdiv(BATCH * HH * WW / 4, 256), 256>>>(imap, out, HH * WW);
}